// round 1
// baseline (speedup 1.0000x reference)
#include <cuda_runtime.h>
#include <math.h>

#define NN   50000
#define EE   1600000
#define DIN  1024
#define HH   256
#define LL   64
#define CC   4
#define NNZ  (EE + NN)

// ---------------- scratch (device globals: no allocation allowed) ----------
__device__ float g_h0[(size_t)NN * HH];
__device__ float g_h [(size_t)NN * HH];
__device__ float g_s [(size_t)NN * HH];
__device__ int   g_deg[NN];
__device__ float g_dinv[NN];
__device__ int   g_rowptr[NN + 1];
__device__ int   g_fill[NN];
__device__ int   g_col[NNZ];
__device__ float g_val[NNZ];

// ---------------- graph preprocessing ----------------

__global__ void k_init_deg() {
    int i = blockIdx.x * blockDim.x + threadIdx.x;
    if (i < NN) g_deg[i] = 1;  // self loop
}

__global__ void k_count(const int* __restrict__ dst) {
    int e = blockIdx.x * blockDim.x + threadIdx.x;
    if (e < EE) atomicAdd(&g_deg[dst[e]], 1);
}

__global__ void k_dinv() {
    int i = blockIdx.x * blockDim.x + threadIdx.x;
    if (i < NN) g_dinv[i] = rsqrtf((float)g_deg[i]);
}

// single-block exclusive scan of g_deg -> g_rowptr (50001 entries)
__global__ void k_scan() {
    __shared__ int sh[1024];
    __shared__ int carry;
    int tid = threadIdx.x;
    if (tid == 0) { carry = 0; g_rowptr[0] = 0; }
    __syncthreads();
    for (int base = 0; base < NN; base += 1024) {
        int i = base + tid;
        int v = (i < NN) ? g_deg[i] : 0;
        sh[tid] = v;
        __syncthreads();
        for (int off = 1; off < 1024; off <<= 1) {
            int t = (tid >= off) ? sh[tid - off] : 0;
            __syncthreads();
            sh[tid] += t;
            __syncthreads();
        }
        if (i < NN) g_rowptr[i + 1] = carry + sh[tid];
        __syncthreads();
        if (tid == 0) carry += sh[1023];
        __syncthreads();
    }
}

__global__ void k_selfloop() {
    int i = blockIdx.x * blockDim.x + threadIdx.x;
    if (i < NN) {
        int p = g_rowptr[i];
        float d = g_dinv[i];
        g_col[p] = i;
        g_val[p] = d * d;
        g_fill[i] = 1;  // self loop occupies slot 0
    }
}

__global__ void k_fill(const int* __restrict__ src, const int* __restrict__ dst) {
    int e = blockIdx.x * blockDim.x + threadIdx.x;
    if (e < EE) {
        int d = dst[e];
        int s = src[e];
        int p = atomicAdd(&g_fill[d], 1);
        int idx = g_rowptr[d] + p;
        g_col[idx] = s;
        g_val[idx] = g_dinv[s] * g_dinv[d];
    }
}

// ---------------- SpMM: s = 0.8 * (A_hat @ h) + 0.2 * h0 ----------------
// one block per node, 256 threads = 256 feature channels
__global__ __launch_bounds__(256) void k_spmm(int first) {
    const float* __restrict__ hin = first ? g_h0 : g_h;
    int row = blockIdx.x;
    int tid = threadIdx.x;
    int s0 = g_rowptr[row];
    int s1 = g_rowptr[row + 1];
    __shared__ int   scol[64];
    __shared__ float sval[64];
    float acc = 0.f;
    for (int e0 = s0; e0 < s1; e0 += 64) {
        int nE = min(64, s1 - e0);
        __syncthreads();
        if (tid < nE) { scol[tid] = g_col[e0 + tid]; sval[tid] = g_val[e0 + tid]; }
        __syncthreads();
        int i = 0;
        for (; i + 4 <= nE; i += 4) {
            float a0 = hin[(size_t)scol[i + 0] * HH + tid];
            float a1 = hin[(size_t)scol[i + 1] * HH + tid];
            float a2 = hin[(size_t)scol[i + 2] * HH + tid];
            float a3 = hin[(size_t)scol[i + 3] * HH + tid];
            acc = fmaf(sval[i + 0], a0, acc);
            acc = fmaf(sval[i + 1], a1, acc);
            acc = fmaf(sval[i + 2], a2, acc);
            acc = fmaf(sval[i + 3], a3, acc);
        }
        for (; i < nE; i++)
            acc = fmaf(sval[i], hin[(size_t)scol[i] * HH + tid], acc);
    }
    size_t o = (size_t)row * HH + tid;
    g_s[o] = 0.8f * acc + 0.2f * g_h0[o];
}

// ---------------- GEMMs (fp32 tiled, 64x64x16, 4x4 microtile) -------------

// projection: g_h0 = x @ projW + projb   (M=NN, K=DIN, Ncol=HH)
__global__ __launch_bounds__(256) void k_gemm_proj(const float* __restrict__ A,
                                                   const float* __restrict__ B,
                                                   const float* __restrict__ bias) {
    const int M = NN, K = DIN, Ncol = HH;
    __shared__ float Ast[16][64];
    __shared__ float Bst[16][64];
    int tid = threadIdx.x;
    int tx = tid & 15, ty = tid >> 4;
    int rowBase = blockIdx.x * 64, colBase = blockIdx.y * 64;
    float acc[4][4] = {};
    for (int k0 = 0; k0 < K; k0 += 16) {
        int idx  = tid * 4;
        int arow = idx >> 4;
        int ak   = idx & 15;
        int grow = rowBase + arow;
        float4 av = make_float4(0.f, 0.f, 0.f, 0.f);
        if (grow < M)
            av = *reinterpret_cast<const float4*>(A + (size_t)grow * K + k0 + ak);
        Ast[ak + 0][arow] = av.x; Ast[ak + 1][arow] = av.y;
        Ast[ak + 2][arow] = av.z; Ast[ak + 3][arow] = av.w;
        int bk = idx >> 6, bn = idx & 63;
        *reinterpret_cast<float4*>(&Bst[bk][bn]) =
            *reinterpret_cast<const float4*>(B + (size_t)(k0 + bk) * Ncol + colBase + bn);
        __syncthreads();
#pragma unroll
        for (int kk = 0; kk < 16; kk++) {
            float ar[4], br[4];
#pragma unroll
            for (int i = 0; i < 4; i++) ar[i] = Ast[kk][ty * 4 + i];
#pragma unroll
            for (int j = 0; j < 4; j++) br[j] = Bst[kk][tx * 4 + j];
#pragma unroll
            for (int i = 0; i < 4; i++)
#pragma unroll
                for (int j = 0; j < 4; j++)
                    acc[i][j] = fmaf(ar[i], br[j], acc[i][j]);
        }
        __syncthreads();
    }
#pragma unroll
    for (int i = 0; i < 4; i++) {
        int r = rowBase + ty * 4 + i;
        if (r < M) {
#pragma unroll
            for (int j = 0; j < 4; j++) {
                int c = colBase + tx * 4 + j;
                g_h0[(size_t)r * Ncol + c] = acc[i][j] + bias[c];
            }
        }
    }
}

// layer: g_h = relu((1-beta)*g_s + beta*(g_s @ W))   (M=NN, K=Ncol=HH)
__global__ __launch_bounds__(256) void k_gemm_layer(const float* __restrict__ B,
                                                    float beta) {
    const int M = NN, K = HH, Ncol = HH;
    const float* __restrict__ A = g_s;
    __shared__ float Ast[16][64];
    __shared__ float Bst[16][64];
    int tid = threadIdx.x;
    int tx = tid & 15, ty = tid >> 4;
    int rowBase = blockIdx.x * 64, colBase = blockIdx.y * 64;
    float acc[4][4] = {};
    for (int k0 = 0; k0 < K; k0 += 16) {
        int idx  = tid * 4;
        int arow = idx >> 4;
        int ak   = idx & 15;
        int grow = rowBase + arow;
        float4 av = make_float4(0.f, 0.f, 0.f, 0.f);
        if (grow < M)
            av = *reinterpret_cast<const float4*>(A + (size_t)grow * K + k0 + ak);
        Ast[ak + 0][arow] = av.x; Ast[ak + 1][arow] = av.y;
        Ast[ak + 2][arow] = av.z; Ast[ak + 3][arow] = av.w;
        int bk = idx >> 6, bn = idx & 63;
        *reinterpret_cast<float4*>(&Bst[bk][bn]) =
            *reinterpret_cast<const float4*>(B + (size_t)(k0 + bk) * Ncol + colBase + bn);
        __syncthreads();
#pragma unroll
        for (int kk = 0; kk < 16; kk++) {
            float ar[4], br[4];
#pragma unroll
            for (int i = 0; i < 4; i++) ar[i] = Ast[kk][ty * 4 + i];
#pragma unroll
            for (int j = 0; j < 4; j++) br[j] = Bst[kk][tx * 4 + j];
#pragma unroll
            for (int i = 0; i < 4; i++)
#pragma unroll
                for (int j = 0; j < 4; j++)
                    acc[i][j] = fmaf(ar[i], br[j], acc[i][j]);
        }
        __syncthreads();
    }
    float omb = 1.0f - beta;
#pragma unroll
    for (int i = 0; i < 4; i++) {
        int r = rowBase + ty * 4 + i;
        if (r < M) {
#pragma unroll
            for (int j = 0; j < 4; j++) {
                int c = colBase + tx * 4 + j;
                float sv = A[(size_t)r * K + c];
                float v = omb * sv + beta * acc[i][j];
                g_h[(size_t)r * Ncol + c] = fmaxf(v, 0.f);
            }
        }
    }
}

// ---------------- classifier: out = g_h @ clsW + clsb --------------------
__global__ void k_cls(const float* __restrict__ Wc, const float* __restrict__ bc,
                      float* __restrict__ out) {
    int gw   = (blockIdx.x * blockDim.x + threadIdx.x) >> 5;
    int lane = threadIdx.x & 31;
    if (gw >= NN) return;
    const float* hr = g_h + (size_t)gw * HH;
    float a0 = 0.f, a1 = 0.f, a2 = 0.f, a3 = 0.f;
    for (int k = lane; k < HH; k += 32) {
        float hv = hr[k];
        const float* w = Wc + k * CC;
        a0 = fmaf(hv, w[0], a0);
        a1 = fmaf(hv, w[1], a1);
        a2 = fmaf(hv, w[2], a2);
        a3 = fmaf(hv, w[3], a3);
    }
#pragma unroll
    for (int off = 16; off; off >>= 1) {
        a0 += __shfl_down_sync(0xffffffffu, a0, off);
        a1 += __shfl_down_sync(0xffffffffu, a1, off);
        a2 += __shfl_down_sync(0xffffffffu, a2, off);
        a3 += __shfl_down_sync(0xffffffffu, a3, off);
    }
    if (lane == 0) {
        out[gw * CC + 0] = a0 + bc[0];
        out[gw * CC + 1] = a1 + bc[1];
        out[gw * CC + 2] = a2 + bc[2];
        out[gw * CC + 3] = a3 + bc[3];
    }
}

// ---------------- launch ----------------

extern "C" void kernel_launch(void* const* d_in, const int* in_sizes, int n_in,
                              void* d_out, int out_size) {
    const float* x     = (const float*)d_in[0];
    const int*   ei    = (const int*)  d_in[1];
    const float* projW = (const float*)d_in[2];
    const float* projb = (const float*)d_in[3];
    const float* wts   = (const float*)d_in[4];
    const float* clsW  = (const float*)d_in[5];
    const float* clsb  = (const float*)d_in[6];
    float* out = (float*)d_out;

    const int* src = ei;
    const int* dst = ei + EE;

    k_init_deg<<<(NN + 255) / 256, 256>>>();
    k_count   <<<(EE + 255) / 256, 256>>>(dst);
    k_dinv    <<<(NN + 255) / 256, 256>>>();
    k_scan    <<<1, 1024>>>();
    k_selfloop<<<(NN + 255) / 256, 256>>>();
    k_fill    <<<(EE + 255) / 256, 256>>>(src, dst);

    dim3 gg((NN + 63) / 64, HH / 64);
    k_gemm_proj<<<gg, 256>>>(x, projW, projb);

    for (int l = 0; l < LL; l++) {
        k_spmm<<<NN, 256>>>(l == 0 ? 1 : 0);
        float beta = logf(0.5f / (float)(l + 1) + 1.0f);
        k_gemm_layer<<<gg, 256>>>(wts + (size_t)l * HH * HH, beta);
    }

    k_cls<<<(NN * 32 + 255) / 256, 256>>>(clsW, clsb, out);
}

// round 6
// speedup vs baseline: 1.4684x; 1.4684x over previous
#include <cuda_runtime.h>
#include <math.h>
#include <stdint.h>

#define NN   50000
#define EE   1600000
#define DIN  1024
#define HH   256
#define LL   64
#define CC   4
#define NNZ  (EE + NN)

// ---------------- scratch (device globals: no allocation allowed) ----------
__device__ float g_h0[(size_t)NN * HH];
__device__ float g_h [(size_t)NN * HH];
__device__ float g_s [(size_t)NN * HH];
__device__ float g_wT[(size_t)LL * HH * HH];   // per-layer W^T, [N][K]
__device__ int   g_deg[NN];
__device__ float g_dinv[NN];
__device__ int   g_rowptr[NN + 1];
__device__ int   g_fill[NN];
__device__ int   g_col[NNZ];
__device__ float g_val[NNZ];

// ---------------- graph preprocessing ----------------

__global__ void k_init_deg() {
    int i = blockIdx.x * blockDim.x + threadIdx.x;
    if (i < NN) g_deg[i] = 1;
}
__global__ void k_count(const int* __restrict__ dst) {
    int e = blockIdx.x * blockDim.x + threadIdx.x;
    if (e < EE) atomicAdd(&g_deg[dst[e]], 1);
}
__global__ void k_dinv() {
    int i = blockIdx.x * blockDim.x + threadIdx.x;
    if (i < NN) g_dinv[i] = rsqrtf((float)g_deg[i]);
}
__global__ void k_scan() {
    __shared__ int sh[1024];
    __shared__ int carry;
    int tid = threadIdx.x;
    if (tid == 0) { carry = 0; g_rowptr[0] = 0; }
    __syncthreads();
    for (int base = 0; base < NN; base += 1024) {
        int i = base + tid;
        int v = (i < NN) ? g_deg[i] : 0;
        sh[tid] = v;
        __syncthreads();
        for (int off = 1; off < 1024; off <<= 1) {
            int t = (tid >= off) ? sh[tid - off] : 0;
            __syncthreads();
            sh[tid] += t;
            __syncthreads();
        }
        if (i < NN) g_rowptr[i + 1] = carry + sh[tid];
        __syncthreads();
        if (tid == 0) carry += sh[1023];
        __syncthreads();
    }
}
__global__ void k_selfloop() {
    int i = blockIdx.x * blockDim.x + threadIdx.x;
    if (i < NN) {
        int p = g_rowptr[i];
        float d = g_dinv[i];
        g_col[p] = i;
        g_val[p] = d * d;
        g_fill[i] = 1;
    }
}
__global__ void k_fill(const int* __restrict__ src, const int* __restrict__ dst) {
    int e = blockIdx.x * blockDim.x + threadIdx.x;
    if (e < EE) {
        int d = dst[e];
        int s = src[e];
        int p = atomicAdd(&g_fill[d], 1);
        int idx = g_rowptr[d] + p;
        g_col[idx] = s;
        g_val[idx] = g_dinv[s] * g_dinv[d];
    }
}

// weight transpose: g_wT[l][n][k] = W[l][k][n]  (W is a real device input ptr)
__global__ void k_transpose_w(const float* __restrict__ W) {
    __shared__ float t[32][33];
    int l = blockIdx.z;
    int n0 = blockIdx.x * 32, k0 = blockIdx.y * 32;
    const float* Wl = W + (size_t)l * HH * HH;
    float* out = g_wT + (size_t)l * HH * HH;
#pragma unroll
    for (int dy = 0; dy < 32; dy += 8)
        t[threadIdx.y + dy][threadIdx.x] = Wl[(size_t)(k0 + threadIdx.y + dy) * HH + n0 + threadIdx.x];
    __syncthreads();
#pragma unroll
    for (int dy = 0; dy < 32; dy += 8)
        out[(size_t)(n0 + threadIdx.y + dy) * HH + k0 + threadIdx.x] = t[threadIdx.x][threadIdx.y + dy];
}

// ---------------- SpMM: s = 0.8 * (A_hat @ h) + 0.2 * h0 ----------------
__global__ __launch_bounds__(256) void k_spmm(int first) {
    const float* __restrict__ hin = first ? g_h0 : g_h;
    int row = blockIdx.x;
    int tid = threadIdx.x;
    int s0 = g_rowptr[row];
    int s1 = g_rowptr[row + 1];
    __shared__ int   scol[64];
    __shared__ float sval[64];
    float acc = 0.f;
    for (int e0 = s0; e0 < s1; e0 += 64) {
        int nE = min(64, s1 - e0);
        __syncthreads();
        if (tid < nE) { scol[tid] = g_col[e0 + tid]; sval[tid] = g_val[e0 + tid]; }
        __syncthreads();
        int i = 0;
        for (; i + 4 <= nE; i += 4) {
            float a0 = hin[(size_t)scol[i + 0] * HH + tid];
            float a1 = hin[(size_t)scol[i + 1] * HH + tid];
            float a2 = hin[(size_t)scol[i + 2] * HH + tid];
            float a3 = hin[(size_t)scol[i + 3] * HH + tid];
            acc = fmaf(sval[i + 0], a0, acc);
            acc = fmaf(sval[i + 1], a1, acc);
            acc = fmaf(sval[i + 2], a2, acc);
            acc = fmaf(sval[i + 3], a3, acc);
        }
        for (; i < nE; i++)
            acc = fmaf(sval[i], hin[(size_t)scol[i] * HH + tid], acc);
    }
    size_t o = (size_t)row * HH + tid;
    g_s[o] = 0.8f * acc + 0.2f * g_h0[o];
}

// ---------------- tf32 mma.sync layer GEMM ----------------
// CTA tile 128x128, 8 warps (4x2), warp tile 32x64, K chunks of 32.
// B tile taken from g_wT (device symbol indexed IN DEVICE CODE via layer idx).
// h = relu((1-beta)*s + beta*(s @ W)).

#define MMA_TF32(ACC, A0, A1, A2, A3, B0, B1)                                \
    asm volatile(                                                            \
        "mma.sync.aligned.m16n8k8.row.col.f32.tf32.tf32.f32 "               \
        "{%0,%1,%2,%3}, {%4,%5,%6,%7}, {%8,%9}, {%0,%1,%2,%3};"             \
        : "+f"((ACC)[0]), "+f"((ACC)[1]), "+f"((ACC)[2]), "+f"((ACC)[3])    \
        : "r"(A0), "r"(A1), "r"(A2), "r"(A3), "r"(B0), "r"(B1))

__global__ __launch_bounds__(256, 2) void k_gemm_mma(int layer, float beta) {
    __shared__ float As[128][36];
    __shared__ float Bs[128][36];

    const float* __restrict__ wTl = g_wT + (size_t)layer * HH * HH;

    int tid = threadIdx.x;
    int wid = tid >> 5;
    int lane = tid & 31;
    int quadRow = lane >> 2;   // 0..7
    int quadCol = lane & 3;    // 0..3
    int warpM = wid >> 1;      // 0..3
    int warpN = wid & 1;       // 0..1
    int mRow = warpM * 32;
    int nBase = warpN * 64;
    int rowBase = blockIdx.x * 128;
    int colBase = blockIdx.y * 128;

    float acc[2][8][4];
#pragma unroll
    for (int i = 0; i < 2; i++)
#pragma unroll
        for (int j = 0; j < 8; j++)
#pragma unroll
            for (int k = 0; k < 4; k++) acc[i][j][k] = 0.f;

    for (int k0 = 0; k0 < HH; k0 += 32) {
#pragma unroll
        for (int i = 0; i < 4; i++) {
            int idx = tid + i * 256;       // 0..1023
            int r = idx >> 3;              // 0..127
            int c = (idx & 7) * 4;         // 0,4,...,28
            int gr = rowBase + r;
            float4 av = make_float4(0.f, 0.f, 0.f, 0.f);
            if (gr < NN)
                av = *reinterpret_cast<const float4*>(g_s + (size_t)gr * HH + k0 + c);
            *reinterpret_cast<float4*>(&As[r][c]) = av;
            *reinterpret_cast<float4*>(&Bs[r][c]) =
                *reinterpret_cast<const float4*>(wTl + (size_t)(colBase + r) * HH + k0 + c);
        }
        __syncthreads();
#pragma unroll
        for (int kk = 0; kk < 32; kk += 8) {
            uint32_t a[2][4];
#pragma unroll
            for (int ma = 0; ma < 2; ma++) {
                int r = mRow + ma * 16 + quadRow;
                a[ma][0] = __float_as_uint(As[r][kk + quadCol]);
                a[ma][1] = __float_as_uint(As[r + 8][kk + quadCol]);
                a[ma][2] = __float_as_uint(As[r][kk + quadCol + 4]);
                a[ma][3] = __float_as_uint(As[r + 8][kk + quadCol + 4]);
            }
#pragma unroll
            for (int nb = 0; nb < 8; nb++) {
                int n = nBase + nb * 8 + quadRow;
                uint32_t b0 = __float_as_uint(Bs[n][kk + quadCol]);
                uint32_t b1 = __float_as_uint(Bs[n][kk + quadCol + 4]);
#pragma unroll
                for (int ma = 0; ma < 2; ma++)
                    MMA_TF32(acc[ma][nb], a[ma][0], a[ma][1], a[ma][2], a[ma][3], b0, b1);
            }
        }
        __syncthreads();
    }

    // epilogue: h = relu((1-beta)*s + beta*acc)
    float omb = 1.0f - beta;
#pragma unroll
    for (int ma = 0; ma < 2; ma++) {
        int r0 = rowBase + mRow + ma * 16 + quadRow;
        int r1 = r0 + 8;
#pragma unroll
        for (int nb = 0; nb < 8; nb++) {
            int c = colBase + nBase + nb * 8 + quadCol * 2;
            if (r0 < NN) {
                float2 sv = *reinterpret_cast<const float2*>(g_s + (size_t)r0 * HH + c);
                float2 o;
                o.x = fmaxf(omb * sv.x + beta * acc[ma][nb][0], 0.f);
                o.y = fmaxf(omb * sv.y + beta * acc[ma][nb][1], 0.f);
                *reinterpret_cast<float2*>(g_h + (size_t)r0 * HH + c) = o;
            }
            if (r1 < NN) {
                float2 sv = *reinterpret_cast<const float2*>(g_s + (size_t)r1 * HH + c);
                float2 o;
                o.x = fmaxf(omb * sv.x + beta * acc[ma][nb][2], 0.f);
                o.y = fmaxf(omb * sv.y + beta * acc[ma][nb][3], 0.f);
                *reinterpret_cast<float2*>(g_h + (size_t)r1 * HH + c) = o;
            }
        }
    }
}

// ---------------- projection GEMM (fp32 SIMT) -------------
__global__ __launch_bounds__(256) void k_gemm_proj(const float* __restrict__ A,
                                                   const float* __restrict__ B,
                                                   const float* __restrict__ bias) {
    const int M = NN, K = DIN, Ncol = HH;
    __shared__ float Ast[16][64];
    __shared__ float Bst[16][64];
    int tid = threadIdx.x;
    int tx = tid & 15, ty = tid >> 4;
    int rowBase = blockIdx.x * 64, colBase = blockIdx.y * 64;
    float acc[4][4] = {};
    for (int k0 = 0; k0 < K; k0 += 16) {
        int idx  = tid * 4;
        int arow = idx >> 4;
        int ak   = idx & 15;
        int grow = rowBase + arow;
        float4 av = make_float4(0.f, 0.f, 0.f, 0.f);
        if (grow < M)
            av = *reinterpret_cast<const float4*>(A + (size_t)grow * K + k0 + ak);
        Ast[ak + 0][arow] = av.x; Ast[ak + 1][arow] = av.y;
        Ast[ak + 2][arow] = av.z; Ast[ak + 3][arow] = av.w;
        int bk = idx >> 6, bn = idx & 63;
        *reinterpret_cast<float4*>(&Bst[bk][bn]) =
            *reinterpret_cast<const float4*>(B + (size_t)(k0 + bk) * Ncol + colBase + bn);
        __syncthreads();
#pragma unroll
        for (int kk = 0; kk < 16; kk++) {
            float ar[4], br[4];
#pragma unroll
            for (int i = 0; i < 4; i++) ar[i] = Ast[kk][ty * 4 + i];
#pragma unroll
            for (int j = 0; j < 4; j++) br[j] = Bst[kk][tx * 4 + j];
#pragma unroll
            for (int i = 0; i < 4; i++)
#pragma unroll
                for (int j = 0; j < 4; j++)
                    acc[i][j] = fmaf(ar[i], br[j], acc[i][j]);
        }
        __syncthreads();
    }
#pragma unroll
    for (int i = 0; i < 4; i++) {
        int r = rowBase + ty * 4 + i;
        if (r < M) {
#pragma unroll
            for (int j = 0; j < 4; j++) {
                int c = colBase + tx * 4 + j;
                g_h0[(size_t)r * Ncol + c] = acc[i][j] + bias[c];
            }
        }
    }
}

// ---------------- classifier ----------------
__global__ void k_cls(const float* __restrict__ Wc, const float* __restrict__ bc,
                      float* __restrict__ out) {
    int gw   = (blockIdx.x * blockDim.x + threadIdx.x) >> 5;
    int lane = threadIdx.x & 31;
    if (gw >= NN) return;
    const float* hr = g_h + (size_t)gw * HH;
    float a0 = 0.f, a1 = 0.f, a2 = 0.f, a3 = 0.f;
    for (int k = lane; k < HH; k += 32) {
        float hv = hr[k];
        const float* w = Wc + k * CC;
        a0 = fmaf(hv, w[0], a0);
        a1 = fmaf(hv, w[1], a1);
        a2 = fmaf(hv, w[2], a2);
        a3 = fmaf(hv, w[3], a3);
    }
#pragma unroll
    for (int off = 16; off; off >>= 1) {
        a0 += __shfl_down_sync(0xffffffffu, a0, off);
        a1 += __shfl_down_sync(0xffffffffu, a1, off);
        a2 += __shfl_down_sync(0xffffffffu, a2, off);
        a3 += __shfl_down_sync(0xffffffffu, a3, off);
    }
    if (lane == 0) {
        out[gw * CC + 0] = a0 + bc[0];
        out[gw * CC + 1] = a1 + bc[1];
        out[gw * CC + 2] = a2 + bc[2];
        out[gw * CC + 3] = a3 + bc[3];
    }
}

// ---------------- launch ----------------

extern "C" void kernel_launch(void* const* d_in, const int* in_sizes, int n_in,
                              void* d_out, int out_size) {
    const float* x     = (const float*)d_in[0];
    const int*   ei    = (const int*)  d_in[1];
    const float* projW = (const float*)d_in[2];
    const float* projb = (const float*)d_in[3];
    const float* wts   = (const float*)d_in[4];
    const float* clsW  = (const float*)d_in[5];
    const float* clsb  = (const float*)d_in[6];
    float* out = (float*)d_out;

    const int* src = ei;
    const int* dst = ei + EE;

    k_init_deg<<<(NN + 255) / 256, 256>>>();
    k_count   <<<(EE + 255) / 256, 256>>>(dst);
    k_dinv    <<<(NN + 255) / 256, 256>>>();
    k_scan    <<<1, 1024>>>();
    k_selfloop<<<(NN + 255) / 256, 256>>>();
    k_fill    <<<(EE + 255) / 256, 256>>>(src, dst);

    dim3 tg(HH / 32, HH / 32, LL);
    k_transpose_w<<<tg, dim3(32, 8)>>>(wts);

    dim3 gg((NN + 63) / 64, HH / 64);
    k_gemm_proj<<<gg, 256>>>(x, projW, projb);

    dim3 mg((NN + 127) / 128, HH / 128);
    for (int l = 0; l < LL; l++) {
        k_spmm<<<NN, 256>>>(l == 0 ? 1 : 0);
        float beta = logf(0.5f / (float)(l + 1) + 1.0f);
        k_gemm_mma<<<mg, 256>>>(l, beta);
    }

    k_cls<<<(NN * 32 + 255) / 256, 256>>>(clsW, clsb, out);
}

// round 7
// speedup vs baseline: 2.0720x; 1.4111x over previous
#include <cuda_runtime.h>
#include <cuda_fp16.h>
#include <math.h>
#include <stdint.h>

#define NN   50000
#define EE   1600000
#define DIN  1024
#define HH   256
#define LL   64
#define CC   4
#define NNZ  (EE + NN)

// ---------------- scratch (device globals: no allocation allowed) ----------
__device__ float   g_h0[(size_t)NN * HH];
__device__ float   g_h [(size_t)NN * HH];
__device__ float   g_s [(size_t)NN * HH];
__device__ __half2 g_hh [(size_t)NN * (HH / 2)];   // fp16 copy of h (gather operand)
__device__ __half2 g_h0h[(size_t)NN * (HH / 2)];   // fp16 copy of h0
__device__ float   g_wT[(size_t)LL * HH * HH];     // per-layer W^T, [N][K]
__device__ int     g_deg[NN];
__device__ float   g_dinv[NN];
__device__ int     g_rowptr[NN + 1];
__device__ int     g_fill[NN];
__device__ int     g_col[NNZ];
__device__ float   g_val[NNZ];

// ---------------- graph preprocessing ----------------

__global__ void k_init_deg() {
    int i = blockIdx.x * blockDim.x + threadIdx.x;
    if (i < NN) g_deg[i] = 1;
}
__global__ void k_count(const int* __restrict__ dst) {
    int e = blockIdx.x * blockDim.x + threadIdx.x;
    if (e < EE) atomicAdd(&g_deg[dst[e]], 1);
}
__global__ void k_dinv() {
    int i = blockIdx.x * blockDim.x + threadIdx.x;
    if (i < NN) g_dinv[i] = rsqrtf((float)g_deg[i]);
}
__global__ void k_scan() {
    __shared__ int sh[1024];
    __shared__ int carry;
    int tid = threadIdx.x;
    if (tid == 0) { carry = 0; g_rowptr[0] = 0; }
    __syncthreads();
    for (int base = 0; base < NN; base += 1024) {
        int i = base + tid;
        int v = (i < NN) ? g_deg[i] : 0;
        sh[tid] = v;
        __syncthreads();
        for (int off = 1; off < 1024; off <<= 1) {
            int t = (tid >= off) ? sh[tid - off] : 0;
            __syncthreads();
            sh[tid] += t;
            __syncthreads();
        }
        if (i < NN) g_rowptr[i + 1] = carry + sh[tid];
        __syncthreads();
        if (tid == 0) carry += sh[1023];
        __syncthreads();
    }
}
__global__ void k_selfloop() {
    int i = blockIdx.x * blockDim.x + threadIdx.x;
    if (i < NN) {
        int p = g_rowptr[i];
        float d = g_dinv[i];
        g_col[p] = i;
        g_val[p] = d * d;
        g_fill[i] = 1;
    }
}
__global__ void k_fill(const int* __restrict__ src, const int* __restrict__ dst) {
    int e = blockIdx.x * blockDim.x + threadIdx.x;
    if (e < EE) {
        int d = dst[e];
        int s = src[e];
        int p = atomicAdd(&g_fill[d], 1);
        int idx = g_rowptr[d] + p;
        g_col[idx] = s;
        g_val[idx] = g_dinv[s] * g_dinv[d];
    }
}

// weight transpose: g_wT[l][n][k] = W[l][k][n]
__global__ void k_transpose_w(const float* __restrict__ W) {
    __shared__ float t[32][33];
    int l = blockIdx.z;
    int n0 = blockIdx.x * 32, k0 = blockIdx.y * 32;
    const float* Wl = W + (size_t)l * HH * HH;
    float* out = g_wT + (size_t)l * HH * HH;
#pragma unroll
    for (int dy = 0; dy < 32; dy += 8)
        t[threadIdx.y + dy][threadIdx.x] = Wl[(size_t)(k0 + threadIdx.y + dy) * HH + n0 + threadIdx.x];
    __syncthreads();
#pragma unroll
    for (int dy = 0; dy < 32; dy += 8)
        out[(size_t)(n0 + threadIdx.y + dy) * HH + k0 + threadIdx.x] = t[threadIdx.x][threadIdx.y + dy];
}

// ---------------- SpMM: s = 0.8 * (A_hat @ h_fp16) + 0.2 * h0 ----------------
// one block per node; 128 threads = 128 half2 lanes (256 feature channels)
__global__ __launch_bounds__(128) void k_spmm(int first) {
    const __half2* __restrict__ hin = first ? g_h0h : g_hh;
    int row = blockIdx.x;
    int tid = threadIdx.x;
    int s0 = g_rowptr[row];
    int s1 = g_rowptr[row + 1];
    __shared__ int   scol[64];
    __shared__ float sval[64];
    float accx = 0.f, accy = 0.f;
    for (int e0 = s0; e0 < s1; e0 += 64) {
        int nE = min(64, s1 - e0);
        __syncthreads();
        if (tid < nE) { scol[tid] = g_col[e0 + tid]; sval[tid] = g_val[e0 + tid]; }
        __syncthreads();
        int i = 0;
        for (; i + 4 <= nE; i += 4) {
            float2 f0 = __half22float2(hin[(size_t)scol[i + 0] * 128 + tid]);
            float2 f1 = __half22float2(hin[(size_t)scol[i + 1] * 128 + tid]);
            float2 f2 = __half22float2(hin[(size_t)scol[i + 2] * 128 + tid]);
            float2 f3 = __half22float2(hin[(size_t)scol[i + 3] * 128 + tid]);
            accx = fmaf(sval[i + 0], f0.x, accx); accy = fmaf(sval[i + 0], f0.y, accy);
            accx = fmaf(sval[i + 1], f1.x, accx); accy = fmaf(sval[i + 1], f1.y, accy);
            accx = fmaf(sval[i + 2], f2.x, accx); accy = fmaf(sval[i + 2], f2.y, accy);
            accx = fmaf(sval[i + 3], f3.x, accx); accy = fmaf(sval[i + 3], f3.y, accy);
        }
        for (; i < nE; i++) {
            float2 f = __half22float2(hin[(size_t)scol[i] * 128 + tid]);
            accx = fmaf(sval[i], f.x, accx);
            accy = fmaf(sval[i], f.y, accy);
        }
    }
    size_t o = (size_t)row * HH + tid * 2;
    float2 h0v = *reinterpret_cast<const float2*>(g_h0 + o);
    float2 sv;
    sv.x = 0.8f * accx + 0.2f * h0v.x;
    sv.y = 0.8f * accy + 0.2f * h0v.y;
    *reinterpret_cast<float2*>(g_s + o) = sv;
}

// ---------------- tf32 mma.sync layer GEMM ----------------
// CTA tile 128x128, 8 warps (4x2), warp tile 32x64, K chunks of 32.
// h = relu((1-beta)*s + beta*(s @ W)); writes fp16 copy always, fp32 only last layer.

#define MMA_TF32(ACC, A0, A1, A2, A3, B0, B1)                                \
    asm volatile(                                                            \
        "mma.sync.aligned.m16n8k8.row.col.f32.tf32.tf32.f32 "               \
        "{%0,%1,%2,%3}, {%4,%5,%6,%7}, {%8,%9}, {%0,%1,%2,%3};"             \
        : "+f"((ACC)[0]), "+f"((ACC)[1]), "+f"((ACC)[2]), "+f"((ACC)[3])    \
        : "r"(A0), "r"(A1), "r"(A2), "r"(A3), "r"(B0), "r"(B1))

__global__ __launch_bounds__(256, 2) void k_gemm_mma(int layer, float beta, int last) {
    __shared__ float As[128][36];
    __shared__ float Bs[128][36];

    const float* __restrict__ wTl = g_wT + (size_t)layer * HH * HH;

    int tid = threadIdx.x;
    int wid = tid >> 5;
    int lane = tid & 31;
    int quadRow = lane >> 2;   // 0..7
    int quadCol = lane & 3;    // 0..3
    int warpM = wid >> 1;      // 0..3
    int warpN = wid & 1;       // 0..1
    int mRow = warpM * 32;
    int nBase = warpN * 64;
    int rowBase = blockIdx.x * 128;
    int colBase = blockIdx.y * 128;

    float acc[2][8][4];
#pragma unroll
    for (int i = 0; i < 2; i++)
#pragma unroll
        for (int j = 0; j < 8; j++)
#pragma unroll
            for (int k = 0; k < 4; k++) acc[i][j][k] = 0.f;

    for (int k0 = 0; k0 < HH; k0 += 32) {
#pragma unroll
        for (int i = 0; i < 4; i++) {
            int idx = tid + i * 256;       // 0..1023
            int r = idx >> 3;              // 0..127
            int c = (idx & 7) * 4;         // 0,4,...,28
            int gr = rowBase + r;
            float4 av = make_float4(0.f, 0.f, 0.f, 0.f);
            if (gr < NN)
                av = *reinterpret_cast<const float4*>(g_s + (size_t)gr * HH + k0 + c);
            *reinterpret_cast<float4*>(&As[r][c]) = av;
            *reinterpret_cast<float4*>(&Bs[r][c]) =
                *reinterpret_cast<const float4*>(wTl + (size_t)(colBase + r) * HH + k0 + c);
        }
        __syncthreads();
#pragma unroll
        for (int kk = 0; kk < 32; kk += 8) {
            uint32_t a[2][4];
#pragma unroll
            for (int ma = 0; ma < 2; ma++) {
                int r = mRow + ma * 16 + quadRow;
                a[ma][0] = __float_as_uint(As[r][kk + quadCol]);
                a[ma][1] = __float_as_uint(As[r + 8][kk + quadCol]);
                a[ma][2] = __float_as_uint(As[r][kk + quadCol + 4]);
                a[ma][3] = __float_as_uint(As[r + 8][kk + quadCol + 4]);
            }
#pragma unroll
            for (int nb = 0; nb < 8; nb++) {
                int n = nBase + nb * 8 + quadRow;
                uint32_t b0 = __float_as_uint(Bs[n][kk + quadCol]);
                uint32_t b1 = __float_as_uint(Bs[n][kk + quadCol + 4]);
#pragma unroll
                for (int ma = 0; ma < 2; ma++)
                    MMA_TF32(acc[ma][nb], a[ma][0], a[ma][1], a[ma][2], a[ma][3], b0, b1);
            }
        }
        __syncthreads();
    }

    // epilogue: h = relu((1-beta)*s + beta*acc); fp16 always, fp32 if last
    float omb = 1.0f - beta;
#pragma unroll
    for (int ma = 0; ma < 2; ma++) {
        int r0 = rowBase + mRow + ma * 16 + quadRow;
        int r1 = r0 + 8;
#pragma unroll
        for (int nb = 0; nb < 8; nb++) {
            int c = colBase + nBase + nb * 8 + quadCol * 2;
            if (r0 < NN) {
                float2 sv = *reinterpret_cast<const float2*>(g_s + (size_t)r0 * HH + c);
                float2 o;
                o.x = fmaxf(omb * sv.x + beta * acc[ma][nb][0], 0.f);
                o.y = fmaxf(omb * sv.y + beta * acc[ma][nb][1], 0.f);
                g_hh[(size_t)r0 * 128 + (c >> 1)] = __floats2half2_rn(o.x, o.y);
                if (last)
                    *reinterpret_cast<float2*>(g_h + (size_t)r0 * HH + c) = o;
            }
            if (r1 < NN) {
                float2 sv = *reinterpret_cast<const float2*>(g_s + (size_t)r1 * HH + c);
                float2 o;
                o.x = fmaxf(omb * sv.x + beta * acc[ma][nb][2], 0.f);
                o.y = fmaxf(omb * sv.y + beta * acc[ma][nb][3], 0.f);
                g_hh[(size_t)r1 * 128 + (c >> 1)] = __floats2half2_rn(o.x, o.y);
                if (last)
                    *reinterpret_cast<float2*>(g_h + (size_t)r1 * HH + c) = o;
            }
        }
    }
}

// ---------------- projection GEMM (fp32 SIMT) -------------
__global__ __launch_bounds__(256) void k_gemm_proj(const float* __restrict__ A,
                                                   const float* __restrict__ B,
                                                   const float* __restrict__ bias) {
    const int M = NN, K = DIN, Ncol = HH;
    __shared__ float Ast[16][64];
    __shared__ float Bst[16][64];
    int tid = threadIdx.x;
    int tx = tid & 15, ty = tid >> 4;
    int rowBase = blockIdx.x * 64, colBase = blockIdx.y * 64;
    float acc[4][4] = {};
    for (int k0 = 0; k0 < K; k0 += 16) {
        int idx  = tid * 4;
        int arow = idx >> 4;
        int ak   = idx & 15;
        int grow = rowBase + arow;
        float4 av = make_float4(0.f, 0.f, 0.f, 0.f);
        if (grow < M)
            av = *reinterpret_cast<const float4*>(A + (size_t)grow * K + k0 + ak);
        Ast[ak + 0][arow] = av.x; Ast[ak + 1][arow] = av.y;
        Ast[ak + 2][arow] = av.z; Ast[ak + 3][arow] = av.w;
        int bk = idx >> 6, bn = idx & 63;
        *reinterpret_cast<float4*>(&Bst[bk][bn]) =
            *reinterpret_cast<const float4*>(B + (size_t)(k0 + bk) * Ncol + colBase + bn);
        __syncthreads();
#pragma unroll
        for (int kk = 0; kk < 16; kk++) {
            float ar[4], br[4];
#pragma unroll
            for (int i = 0; i < 4; i++) ar[i] = Ast[kk][ty * 4 + i];
#pragma unroll
            for (int j = 0; j < 4; j++) br[j] = Bst[kk][tx * 4 + j];
#pragma unroll
            for (int i = 0; i < 4; i++)
#pragma unroll
                for (int j = 0; j < 4; j++)
                    acc[i][j] = fmaf(ar[i], br[j], acc[i][j]);
        }
        __syncthreads();
    }
#pragma unroll
    for (int i = 0; i < 4; i++) {
        int r = rowBase + ty * 4 + i;
        if (r < M) {
#pragma unroll
            for (int j = 0; j < 4; j += 2) {
                int c = colBase + tx * 4 + j;
                float vx = acc[i][j] + bias[c];
                float vy = acc[i][j + 1] + bias[c + 1];
                g_h0[(size_t)r * Ncol + c]     = vx;
                g_h0[(size_t)r * Ncol + c + 1] = vy;
                g_h0h[(size_t)r * 128 + (c >> 1)] = __floats2half2_rn(vx, vy);
            }
        }
    }
}

// ---------------- classifier ----------------
__global__ void k_cls(const float* __restrict__ Wc, const float* __restrict__ bc,
                      float* __restrict__ out) {
    int gw   = (blockIdx.x * blockDim.x + threadIdx.x) >> 5;
    int lane = threadIdx.x & 31;
    if (gw >= NN) return;
    const float* hr = g_h + (size_t)gw * HH;
    float a0 = 0.f, a1 = 0.f, a2 = 0.f, a3 = 0.f;
    for (int k = lane; k < HH; k += 32) {
        float hv = hr[k];
        const float* w = Wc + k * CC;
        a0 = fmaf(hv, w[0], a0);
        a1 = fmaf(hv, w[1], a1);
        a2 = fmaf(hv, w[2], a2);
        a3 = fmaf(hv, w[3], a3);
    }
#pragma unroll
    for (int off = 16; off; off >>= 1) {
        a0 += __shfl_down_sync(0xffffffffu, a0, off);
        a1 += __shfl_down_sync(0xffffffffu, a1, off);
        a2 += __shfl_down_sync(0xffffffffu, a2, off);
        a3 += __shfl_down_sync(0xffffffffu, a3, off);
    }
    if (lane == 0) {
        out[gw * CC + 0] = a0 + bc[0];
        out[gw * CC + 1] = a1 + bc[1];
        out[gw * CC + 2] = a2 + bc[2];
        out[gw * CC + 3] = a3 + bc[3];
    }
}

// ---------------- launch ----------------

extern "C" void kernel_launch(void* const* d_in, const int* in_sizes, int n_in,
                              void* d_out, int out_size) {
    const float* x     = (const float*)d_in[0];
    const int*   ei    = (const int*)  d_in[1];
    const float* projW = (const float*)d_in[2];
    const float* projb = (const float*)d_in[3];
    const float* wts   = (const float*)d_in[4];
    const float* clsW  = (const float*)d_in[5];
    const float* clsb  = (const float*)d_in[6];
    float* out = (float*)d_out;

    const int* src = ei;
    const int* dst = ei + EE;

    k_init_deg<<<(NN + 255) / 256, 256>>>();
    k_count   <<<(EE + 255) / 256, 256>>>(dst);
    k_dinv    <<<(NN + 255) / 256, 256>>>();
    k_scan    <<<1, 1024>>>();
    k_selfloop<<<(NN + 255) / 256, 256>>>();
    k_fill    <<<(EE + 255) / 256, 256>>>(src, dst);

    dim3 tg(HH / 32, HH / 32, LL);
    k_transpose_w<<<tg, dim3(32, 8)>>>(wts);

    dim3 gg((NN + 63) / 64, HH / 64);
    k_gemm_proj<<<gg, 256>>>(x, projW, projb);

    dim3 mg((NN + 127) / 128, HH / 128);
    for (int l = 0; l < LL; l++) {
        k_spmm<<<NN, 128>>>(l == 0 ? 1 : 0);
        float beta = logf(0.5f / (float)(l + 1) + 1.0f);
        k_gemm_mma<<<mg, 256>>>(l, beta, l == LL - 1 ? 1 : 0);
    }

    k_cls<<<(NN * 32 + 255) / 256, 256>>>(clsW, clsb, out);
}

// round 9
// speedup vs baseline: 2.3223x; 1.1208x over previous
#include <cuda_runtime.h>
#include <cuda_fp16.h>
#include <math.h>
#include <stdint.h>

#define NN   50000
#define EE   1600000
#define DIN  1024
#define HH   256
#define LL   64
#define CC   4
#define NNZ  (EE + NN)

// ---------------- scratch (device globals: no allocation allowed) ----------
__device__ float   g_h0[(size_t)NN * HH];
__device__ float   g_h [(size_t)NN * HH];
__device__ float   g_s [(size_t)NN * HH];
__device__ __half2 g_hh [(size_t)NN * (HH / 2)];    // fp16 h   (SpMM gather operand)
__device__ __half2 g_h0h[(size_t)NN * (HH / 2)];    // fp16 h0
__device__ __half2 g_sh [(size_t)NN * (HH / 2)];    // fp16 s   (layer-GEMM A operand)
__device__ __half2 g_xh [(size_t)NN * (DIN / 2)];   // fp16 x   (proj-GEMM A operand)
__device__ __half2 g_wTh[(size_t)LL * HH * (HH / 2)];  // fp16 W^T per layer [N][K/2]
__device__ __half2 g_pWh[(size_t)HH * (DIN / 2)];      // fp16 projW^T [N=256][K=1024/2]
__device__ int     g_deg[NN];
__device__ float   g_dinv[NN];
__device__ int     g_rowptr[NN + 1];
__device__ int     g_fill[NN];
__device__ int     g_col[NNZ];
__device__ float   g_val[NNZ];

// ---------------- graph preprocessing ----------------

__global__ void k_init_deg() {
    int i = blockIdx.x * blockDim.x + threadIdx.x;
    if (i < NN) g_deg[i] = 1;
}
__global__ void k_count(const int* __restrict__ dst) {
    int e = blockIdx.x * blockDim.x + threadIdx.x;
    if (e < EE) atomicAdd(&g_deg[dst[e]], 1);
}
__global__ void k_dinv() {
    int i = blockIdx.x * blockDim.x + threadIdx.x;
    if (i < NN) g_dinv[i] = rsqrtf((float)g_deg[i]);
}
__global__ void k_scan() {
    __shared__ int sh[1024];
    __shared__ int carry;
    int tid = threadIdx.x;
    if (tid == 0) { carry = 0; g_rowptr[0] = 0; }
    __syncthreads();
    for (int base = 0; base < NN; base += 1024) {
        int i = base + tid;
        int v = (i < NN) ? g_deg[i] : 0;
        sh[tid] = v;
        __syncthreads();
        for (int off = 1; off < 1024; off <<= 1) {
            int t = (tid >= off) ? sh[tid - off] : 0;
            __syncthreads();
            sh[tid] += t;
            __syncthreads();
        }
        if (i < NN) g_rowptr[i + 1] = carry + sh[tid];
        __syncthreads();
        if (tid == 0) carry += sh[1023];
        __syncthreads();
    }
}
__global__ void k_selfloop() {
    int i = blockIdx.x * blockDim.x + threadIdx.x;
    if (i < NN) {
        int p = g_rowptr[i];
        float d = g_dinv[i];
        g_col[p] = i;
        g_val[p] = d * d;
        g_fill[i] = 1;
    }
}
__global__ void k_fill(const int* __restrict__ src, const int* __restrict__ dst) {
    int e = blockIdx.x * blockDim.x + threadIdx.x;
    if (e < EE) {
        int d = dst[e];
        int s = src[e];
        int p = atomicAdd(&g_fill[d], 1);
        int idx = g_rowptr[d] + p;
        g_col[idx] = s;
        g_val[idx] = g_dinv[s] * g_dinv[d];
    }
}

// weight transpose to fp16: g_wTh[l][n][k] = (half)W[l][k][n]
__global__ void k_transpose_w(const float* __restrict__ W) {
    __shared__ float t[32][33];
    int l = blockIdx.z;
    int n0 = blockIdx.x * 32, k0 = blockIdx.y * 32;
    const float* Wl = W + (size_t)l * HH * HH;
    __half* out = reinterpret_cast<__half*>(g_wTh) + (size_t)l * HH * HH;
#pragma unroll
    for (int dy = 0; dy < 32; dy += 8)
        t[threadIdx.y + dy][threadIdx.x] = Wl[(size_t)(k0 + threadIdx.y + dy) * HH + n0 + threadIdx.x];
    __syncthreads();
#pragma unroll
    for (int dy = 0; dy < 32; dy += 8)
        out[(size_t)(n0 + threadIdx.y + dy) * HH + k0 + threadIdx.x] =
            __float2half_rn(t[threadIdx.x][threadIdx.y + dy]);
}

// projW transpose to fp16: g_pWh[n][k] = (half)projW[k][n]  (projW is [1024][256])
__global__ void k_transpose_pw(const float* __restrict__ PW) {
    __shared__ float t[32][33];
    int n0 = blockIdx.x * 32, k0 = blockIdx.y * 32;
    __half* out = reinterpret_cast<__half*>(g_pWh);
#pragma unroll
    for (int dy = 0; dy < 32; dy += 8)
        t[threadIdx.y + dy][threadIdx.x] = PW[(size_t)(k0 + threadIdx.y + dy) * HH + n0 + threadIdx.x];
    __syncthreads();
#pragma unroll
    for (int dy = 0; dy < 32; dy += 8)
        out[(size_t)(n0 + threadIdx.y + dy) * DIN + k0 + threadIdx.x] =
            __float2half_rn(t[threadIdx.x][threadIdx.y + dy]);
}

// x -> fp16
__global__ void k_x2h(const float* __restrict__ x) {
    int i = blockIdx.x * blockDim.x + threadIdx.x;   // float4 index
    const int total = NN * DIN / 4;
    if (i < total) {
        float4 v = reinterpret_cast<const float4*>(x)[i];
        g_xh[i * 2 + 0] = __floats2half2_rn(v.x, v.y);
        g_xh[i * 2 + 1] = __floats2half2_rn(v.z, v.w);
    }
}

// ---------------- SpMM: s = 0.8 * (A_hat @ h_fp16) + 0.2 * h0 ----------------
__global__ __launch_bounds__(128) void k_spmm(int first) {
    const __half2* __restrict__ hin = first ? g_h0h : g_hh;
    int row = blockIdx.x;
    int tid = threadIdx.x;
    int s0 = g_rowptr[row];
    int s1 = g_rowptr[row + 1];
    __shared__ int   scol[64];
    __shared__ float sval[64];
    float accx = 0.f, accy = 0.f;
    for (int e0 = s0; e0 < s1; e0 += 64) {
        int nE = min(64, s1 - e0);
        __syncthreads();
        if (tid < nE) { scol[tid] = g_col[e0 + tid]; sval[tid] = g_val[e0 + tid]; }
        __syncthreads();
        int i = 0;
        for (; i + 4 <= nE; i += 4) {
            float2 f0 = __half22float2(hin[(size_t)scol[i + 0] * 128 + tid]);
            float2 f1 = __half22float2(hin[(size_t)scol[i + 1] * 128 + tid]);
            float2 f2 = __half22float2(hin[(size_t)scol[i + 2] * 128 + tid]);
            float2 f3 = __half22float2(hin[(size_t)scol[i + 3] * 128 + tid]);
            accx = fmaf(sval[i + 0], f0.x, accx); accy = fmaf(sval[i + 0], f0.y, accy);
            accx = fmaf(sval[i + 1], f1.x, accx); accy = fmaf(sval[i + 1], f1.y, accy);
            accx = fmaf(sval[i + 2], f2.x, accx); accy = fmaf(sval[i + 2], f2.y, accy);
            accx = fmaf(sval[i + 3], f3.x, accx); accy = fmaf(sval[i + 3], f3.y, accy);
        }
        for (; i < nE; i++) {
            float2 f = __half22float2(hin[(size_t)scol[i] * 128 + tid]);
            accx = fmaf(sval[i], f.x, accx);
            accy = fmaf(sval[i], f.y, accy);
        }
    }
    size_t o = (size_t)row * HH + tid * 2;
    float2 h0v = *reinterpret_cast<const float2*>(g_h0 + o);
    float2 sv;
    sv.x = 0.8f * accx + 0.2f * h0v.x;
    sv.y = 0.8f * accy + 0.2f * h0v.y;
    *reinterpret_cast<float2*>(g_s + o) = sv;
    g_sh[(size_t)row * 128 + tid] = __floats2half2_rn(sv.x, sv.y);
}

// ---------------- fp16 mma.m16n8k16 GEMM core ----------------
// CTA tile 128x128, 8 warps (4x2), warp tile 32x64, K chunks of 64 halves.

#define MMA_F16(ACC, A0, A1, A2, A3, B0, B1)                                 \
    asm volatile(                                                            \
        "mma.sync.aligned.m16n8k16.row.col.f32.f16.f16.f32 "                \
        "{%0,%1,%2,%3}, {%4,%5,%6,%7}, {%8,%9}, {%0,%1,%2,%3};"             \
        : "+f"((ACC)[0]), "+f"((ACC)[1]), "+f"((ACC)[2]), "+f"((ACC)[3])    \
        : "r"(A0), "r"(A1), "r"(A2), "r"(A3), "r"(B0), "r"(B1))

// layer GEMM: h = relu((1-beta)*s + beta*(s@W)); A = g_sh, B = g_wTh[layer]
// grid = ((NN+127)/128, HH/128=2); blockIdx.y selects the 128-wide N slab.
__global__ __launch_bounds__(256, 2) void k_gemm_mma(int layer, float beta, int last) {
    __shared__ __half2 As[128][36];
    __shared__ __half2 Bs[128][36];

    const __half2* __restrict__ wTl = g_wTh + (size_t)layer * HH * 128;

    int tid = threadIdx.x;
    int wid = tid >> 5;
    int lane = tid & 31;
    int quadRow = lane >> 2;
    int quadCol = lane & 3;
    int warpM = wid >> 1;
    int warpN = wid & 1;
    int mRow = warpM * 32;
    int nBase = warpN * 64;
    int rowBase = blockIdx.x * 128;
    int colBase = blockIdx.y * 128;

    float acc[2][8][4];
#pragma unroll
    for (int i = 0; i < 2; i++)
#pragma unroll
        for (int j = 0; j < 8; j++)
#pragma unroll
            for (int k = 0; k < 4; k++) acc[i][j][k] = 0.f;

    for (int ch = 0; ch < 4; ch++) {
        int k2 = ch * 32;   // h2 offset
#pragma unroll
        for (int i = 0; i < 4; i++) {
            int idx = tid + i * 256;       // 0..1023
            int r = idx >> 3;              // 0..127
            int c2 = (idx & 7) * 4;        // h2 col 0,4,...,28
            int gr = rowBase + r;
            float4 av = make_float4(0.f, 0.f, 0.f, 0.f);
            if (gr < NN)
                av = *reinterpret_cast<const float4*>(g_sh + (size_t)gr * 128 + k2 + c2);
            *reinterpret_cast<float4*>(&As[r][c2]) = av;
            *reinterpret_cast<float4*>(&Bs[r][c2]) =
                *reinterpret_cast<const float4*>(wTl + (size_t)(colBase + r) * 128 + k2 + c2);
        }
        __syncthreads();
#pragma unroll
        for (int kk2 = 0; kk2 < 32; kk2 += 8) {   // 4 k16 steps per chunk
            uint32_t a[2][4];
#pragma unroll
            for (int ma = 0; ma < 2; ma++) {
                int r = mRow + ma * 16 + quadRow;
                a[ma][0] = *reinterpret_cast<uint32_t*>(&As[r][kk2 + quadCol]);
                a[ma][1] = *reinterpret_cast<uint32_t*>(&As[r + 8][kk2 + quadCol]);
                a[ma][2] = *reinterpret_cast<uint32_t*>(&As[r][kk2 + quadCol + 4]);
                a[ma][3] = *reinterpret_cast<uint32_t*>(&As[r + 8][kk2 + quadCol + 4]);
            }
#pragma unroll
            for (int nb = 0; nb < 8; nb++) {
                int n = nBase + nb * 8 + quadRow;
                uint32_t b0 = *reinterpret_cast<uint32_t*>(&Bs[n][kk2 + quadCol]);
                uint32_t b1 = *reinterpret_cast<uint32_t*>(&Bs[n][kk2 + quadCol + 4]);
#pragma unroll
                for (int ma = 0; ma < 2; ma++)
                    MMA_F16(acc[ma][nb], a[ma][0], a[ma][1], a[ma][2], a[ma][3], b0, b1);
            }
        }
        __syncthreads();
    }

    float omb = 1.0f - beta;
#pragma unroll
    for (int ma = 0; ma < 2; ma++) {
        int r0 = rowBase + mRow + ma * 16 + quadRow;
        int r1 = r0 + 8;
#pragma unroll
        for (int nb = 0; nb < 8; nb++) {
            int c = colBase + nBase + nb * 8 + quadCol * 2;
            if (r0 < NN) {
                float2 sv = *reinterpret_cast<const float2*>(g_s + (size_t)r0 * HH + c);
                float2 o;
                o.x = fmaxf(omb * sv.x + beta * acc[ma][nb][0], 0.f);
                o.y = fmaxf(omb * sv.y + beta * acc[ma][nb][1], 0.f);
                g_hh[(size_t)r0 * 128 + (c >> 1)] = __floats2half2_rn(o.x, o.y);
                if (last)
                    *reinterpret_cast<float2*>(g_h + (size_t)r0 * HH + c) = o;
            }
            if (r1 < NN) {
                float2 sv = *reinterpret_cast<const float2*>(g_s + (size_t)r1 * HH + c);
                float2 o;
                o.x = fmaxf(omb * sv.x + beta * acc[ma][nb][2], 0.f);
                o.y = fmaxf(omb * sv.y + beta * acc[ma][nb][3], 0.f);
                g_hh[(size_t)r1 * 128 + (c >> 1)] = __floats2half2_rn(o.x, o.y);
                if (last)
                    *reinterpret_cast<float2*>(g_h + (size_t)r1 * HH + c) = o;
            }
        }
    }
}

// projection GEMM fp16: h0 = x @ projW + b; A = g_xh [NN][512 h2], B = g_pWh [256][512 h2]
__global__ __launch_bounds__(256, 2) void k_gemm_proj(const float* __restrict__ bias) {
    __shared__ __half2 As[128][36];
    __shared__ __half2 Bs[128][36];

    int tid = threadIdx.x;
    int wid = tid >> 5;
    int lane = tid & 31;
    int quadRow = lane >> 2;
    int quadCol = lane & 3;
    int warpM = wid >> 1;
    int warpN = wid & 1;
    int mRow = warpM * 32;
    int nBase = warpN * 64;
    int rowBase = blockIdx.x * 128;
    int colBase = blockIdx.y * 128;

    float acc[2][8][4];
#pragma unroll
    for (int i = 0; i < 2; i++)
#pragma unroll
        for (int j = 0; j < 8; j++)
#pragma unroll
            for (int k = 0; k < 4; k++) acc[i][j][k] = 0.f;

    for (int ch = 0; ch < 16; ch++) {   // K = 1024 halves = 16 chunks of 64
        int k2 = ch * 32;
#pragma unroll
        for (int i = 0; i < 4; i++) {
            int idx = tid + i * 256;
            int r = idx >> 3;
            int c2 = (idx & 7) * 4;
            int gr = rowBase + r;
            float4 av = make_float4(0.f, 0.f, 0.f, 0.f);
            if (gr < NN)
                av = *reinterpret_cast<const float4*>(g_xh + (size_t)gr * 512 + k2 + c2);
            *reinterpret_cast<float4*>(&As[r][c2]) = av;
            *reinterpret_cast<float4*>(&Bs[r][c2]) =
                *reinterpret_cast<const float4*>(g_pWh + (size_t)(colBase + r) * 512 + k2 + c2);
        }
        __syncthreads();
#pragma unroll
        for (int kk2 = 0; kk2 < 32; kk2 += 8) {
            uint32_t a[2][4];
#pragma unroll
            for (int ma = 0; ma < 2; ma++) {
                int r = mRow + ma * 16 + quadRow;
                a[ma][0] = *reinterpret_cast<uint32_t*>(&As[r][kk2 + quadCol]);
                a[ma][1] = *reinterpret_cast<uint32_t*>(&As[r + 8][kk2 + quadCol]);
                a[ma][2] = *reinterpret_cast<uint32_t*>(&As[r][kk2 + quadCol + 4]);
                a[ma][3] = *reinterpret_cast<uint32_t*>(&As[r + 8][kk2 + quadCol + 4]);
            }
#pragma unroll
            for (int nb = 0; nb < 8; nb++) {
                int n = nBase + nb * 8 + quadRow;
                uint32_t b0 = *reinterpret_cast<uint32_t*>(&Bs[n][kk2 + quadCol]);
                uint32_t b1 = *reinterpret_cast<uint32_t*>(&Bs[n][kk2 + quadCol + 4]);
#pragma unroll
                for (int ma = 0; ma < 2; ma++)
                    MMA_F16(acc[ma][nb], a[ma][0], a[ma][1], a[ma][2], a[ma][3], b0, b1);
            }
        }
        __syncthreads();
    }

#pragma unroll
    for (int ma = 0; ma < 2; ma++) {
        int r0 = rowBase + mRow + ma * 16 + quadRow;
        int r1 = r0 + 8;
#pragma unroll
        for (int nb = 0; nb < 8; nb++) {
            int c = colBase + nBase + nb * 8 + quadCol * 2;
            float bx = bias[c], by = bias[c + 1];
            if (r0 < NN) {
                float vx = acc[ma][nb][0] + bx;
                float vy = acc[ma][nb][1] + by;
                *reinterpret_cast<float2*>(g_h0 + (size_t)r0 * HH + c) = make_float2(vx, vy);
                g_h0h[(size_t)r0 * 128 + (c >> 1)] = __floats2half2_rn(vx, vy);
            }
            if (r1 < NN) {
                float vx = acc[ma][nb][2] + bx;
                float vy = acc[ma][nb][3] + by;
                *reinterpret_cast<float2*>(g_h0 + (size_t)r1 * HH + c) = make_float2(vx, vy);
                g_h0h[(size_t)r1 * 128 + (c >> 1)] = __floats2half2_rn(vx, vy);
            }
        }
    }
}

// ---------------- classifier ----------------
__global__ void k_cls(const float* __restrict__ Wc, const float* __restrict__ bc,
                      float* __restrict__ out) {
    int gw   = (blockIdx.x * blockDim.x + threadIdx.x) >> 5;
    int lane = threadIdx.x & 31;
    if (gw >= NN) return;
    const float* hr = g_h + (size_t)gw * HH;
    float a0 = 0.f, a1 = 0.f, a2 = 0.f, a3 = 0.f;
    for (int k = lane; k < HH; k += 32) {
        float hv = hr[k];
        const float* w = Wc + k * CC;
        a0 = fmaf(hv, w[0], a0);
        a1 = fmaf(hv, w[1], a1);
        a2 = fmaf(hv, w[2], a2);
        a3 = fmaf(hv, w[3], a3);
    }
#pragma unroll
    for (int off = 16; off; off >>= 1) {
        a0 += __shfl_down_sync(0xffffffffu, a0, off);
        a1 += __shfl_down_sync(0xffffffffu, a1, off);
        a2 += __shfl_down_sync(0xffffffffu, a2, off);
        a3 += __shfl_down_sync(0xffffffffu, a3, off);
    }
    if (lane == 0) {
        out[gw * CC + 0] = a0 + bc[0];
        out[gw * CC + 1] = a1 + bc[1];
        out[gw * CC + 2] = a2 + bc[2];
        out[gw * CC + 3] = a3 + bc[3];
    }
}

// ---------------- launch ----------------

extern "C" void kernel_launch(void* const* d_in, const int* in_sizes, int n_in,
                              void* d_out, int out_size) {
    const float* x     = (const float*)d_in[0];
    const int*   ei    = (const int*)  d_in[1];
    const float* projW = (const float*)d_in[2];
    const float* projb = (const float*)d_in[3];
    const float* wts   = (const float*)d_in[4];
    const float* clsW  = (const float*)d_in[5];
    const float* clsb  = (const float*)d_in[6];
    float* out = (float*)d_out;

    const int* src = ei;
    const int* dst = ei + EE;

    k_init_deg<<<(NN + 255) / 256, 256>>>();
    k_count   <<<(EE + 255) / 256, 256>>>(dst);
    k_dinv    <<<(NN + 255) / 256, 256>>>();
    k_scan    <<<1, 1024>>>();
    k_selfloop<<<(NN + 255) / 256, 256>>>();
    k_fill    <<<(EE + 255) / 256, 256>>>(src, dst);

    dim3 tg(HH / 32, HH / 32, LL);
    k_transpose_w<<<tg, dim3(32, 8)>>>(wts);
    dim3 pg(HH / 32, DIN / 32);
    k_transpose_pw<<<pg, dim3(32, 8)>>>(projW);
    k_x2h<<<(NN * DIN / 4 + 255) / 256, 256>>>(x);

    dim3 gg((NN + 127) / 128, 2);
    k_gemm_proj<<<gg, 256>>>(projb);

    dim3 mg((NN + 127) / 128, HH / 128);   // 2 column slabs — covers all 256 cols
    for (int l = 0; l < LL; l++) {
        k_spmm<<<NN, 128>>>(l == 0 ? 1 : 0);
        float beta = logf(0.5f / (float)(l + 1) + 1.0f);
        k_gemm_mma<<<mg, 256>>>(l, beta, l == LL - 1 ? 1 : 0);
    }

    k_cls<<<(NN * 32 + 255) / 256, 256>>>(clsW, clsb, out);
}

// round 10
// speedup vs baseline: 2.3250x; 1.0012x over previous
#include <cuda_runtime.h>
#include <cuda_fp16.h>
#include <math.h>
#include <stdint.h>

#define NN   50000
#define EE   1600000
#define DIN  1024
#define HH   256
#define LL   64
#define CC   4
#define NNZ  (EE + NN)

// ---------------- scratch (device globals: no allocation allowed) ----------
__device__ float   g_h0[(size_t)NN * HH];
__device__ float   g_h [(size_t)NN * HH];
__device__ float   g_s [(size_t)NN * HH];
__device__ __half2 g_hh [(size_t)NN * (HH / 2)];
__device__ __half2 g_h0h[(size_t)NN * (HH / 2)];
__device__ __half2 g_sh [(size_t)NN * (HH / 2)];
__device__ __half2 g_xh [(size_t)NN * (DIN / 2)];
__device__ __half2 g_wTh[(size_t)LL * HH * (HH / 2)];
__device__ __half2 g_pWh[(size_t)HH * (DIN / 2)];
__device__ int     g_deg[NN];
__device__ float   g_dinv[NN];
__device__ int     g_rowptr[NN + 1];
__device__ int     g_fill[NN];
__device__ int     g_col[NNZ];
__device__ float   g_val[NNZ];

// ---------------- graph preprocessing ----------------

__global__ void k_init_deg() {
    int i = blockIdx.x * blockDim.x + threadIdx.x;
    if (i < NN) g_deg[i] = 1;
}
__global__ void k_count(const int* __restrict__ dst) {
    int e = blockIdx.x * blockDim.x + threadIdx.x;
    if (e < EE) atomicAdd(&g_deg[dst[e]], 1);
}
__global__ void k_dinv() {
    int i = blockIdx.x * blockDim.x + threadIdx.x;
    if (i < NN) g_dinv[i] = rsqrtf((float)g_deg[i]);
}
__global__ void k_scan() {
    __shared__ int sh[1024];
    __shared__ int carry;
    int tid = threadIdx.x;
    if (tid == 0) { carry = 0; g_rowptr[0] = 0; }
    __syncthreads();
    for (int base = 0; base < NN; base += 1024) {
        int i = base + tid;
        int v = (i < NN) ? g_deg[i] : 0;
        sh[tid] = v;
        __syncthreads();
        for (int off = 1; off < 1024; off <<= 1) {
            int t = (tid >= off) ? sh[tid - off] : 0;
            __syncthreads();
            sh[tid] += t;
            __syncthreads();
        }
        if (i < NN) g_rowptr[i + 1] = carry + sh[tid];
        __syncthreads();
        if (tid == 0) carry += sh[1023];
        __syncthreads();
    }
}
__global__ void k_selfloop() {
    int i = blockIdx.x * blockDim.x + threadIdx.x;
    if (i < NN) {
        int p = g_rowptr[i];
        float d = g_dinv[i];
        g_col[p] = i;
        g_val[p] = d * d;
        g_fill[i] = 1;
    }
}
__global__ void k_fill(const int* __restrict__ src, const int* __restrict__ dst) {
    int e = blockIdx.x * blockDim.x + threadIdx.x;
    if (e < EE) {
        int d = dst[e];
        int s = src[e];
        int p = atomicAdd(&g_fill[d], 1);
        int idx = g_rowptr[d] + p;
        g_col[idx] = s;
        g_val[idx] = g_dinv[s] * g_dinv[d];
    }
}

// weight transpose to fp16: g_wTh[l][n][k] = (half)W[l][k][n]
__global__ void k_transpose_w(const float* __restrict__ W) {
    __shared__ float t[32][33];
    int l = blockIdx.z;
    int n0 = blockIdx.x * 32, k0 = blockIdx.y * 32;
    const float* Wl = W + (size_t)l * HH * HH;
    __half* out = reinterpret_cast<__half*>(g_wTh) + (size_t)l * HH * HH;
#pragma unroll
    for (int dy = 0; dy < 32; dy += 8)
        t[threadIdx.y + dy][threadIdx.x] = Wl[(size_t)(k0 + threadIdx.y + dy) * HH + n0 + threadIdx.x];
    __syncthreads();
#pragma unroll
    for (int dy = 0; dy < 32; dy += 8)
        out[(size_t)(n0 + threadIdx.y + dy) * HH + k0 + threadIdx.x] =
            __float2half_rn(t[threadIdx.x][threadIdx.y + dy]);
}

// projW transpose to fp16: g_pWh[n][k] = (half)projW[k][n]
__global__ void k_transpose_pw(const float* __restrict__ PW) {
    __shared__ float t[32][33];
    int n0 = blockIdx.x * 32, k0 = blockIdx.y * 32;
    __half* out = reinterpret_cast<__half*>(g_pWh);
#pragma unroll
    for (int dy = 0; dy < 32; dy += 8)
        t[threadIdx.y + dy][threadIdx.x] = PW[(size_t)(k0 + threadIdx.y + dy) * HH + n0 + threadIdx.x];
    __syncthreads();
#pragma unroll
    for (int dy = 0; dy < 32; dy += 8)
        out[(size_t)(n0 + threadIdx.y + dy) * DIN + k0 + threadIdx.x] =
            __float2half_rn(t[threadIdx.x][threadIdx.y + dy]);
}

// x -> fp16
__global__ void k_x2h(const float* __restrict__ x) {
    int i = blockIdx.x * blockDim.x + threadIdx.x;
    const int total = NN * DIN / 4;
    if (i < total) {
        float4 v = reinterpret_cast<const float4*>(x)[i];
        g_xh[i * 2 + 0] = __floats2half2_rn(v.x, v.y);
        g_xh[i * 2 + 1] = __floats2half2_rn(v.z, v.w);
    }
}

// ---------------- SpMM: s = 0.8 * (A_hat @ h_fp16) + 0.2 * h0 ----------------
__global__ __launch_bounds__(128) void k_spmm(int first) {
    const __half2* __restrict__ hin = first ? g_h0h : g_hh;
    int row = blockIdx.x;
    int tid = threadIdx.x;
    int s0 = g_rowptr[row];
    int s1 = g_rowptr[row + 1];
    __shared__ int   scol[64];
    __shared__ float sval[64];
    float accx = 0.f, accy = 0.f;
    for (int e0 = s0; e0 < s1; e0 += 64) {
        int nE = min(64, s1 - e0);
        __syncthreads();
        if (tid < nE) { scol[tid] = g_col[e0 + tid]; sval[tid] = g_val[e0 + tid]; }
        __syncthreads();
        int i = 0;
        for (; i + 4 <= nE; i += 4) {
            float2 f0 = __half22float2(hin[(size_t)scol[i + 0] * 128 + tid]);
            float2 f1 = __half22float2(hin[(size_t)scol[i + 1] * 128 + tid]);
            float2 f2 = __half22float2(hin[(size_t)scol[i + 2] * 128 + tid]);
            float2 f3 = __half22float2(hin[(size_t)scol[i + 3] * 128 + tid]);
            accx = fmaf(sval[i + 0], f0.x, accx); accy = fmaf(sval[i + 0], f0.y, accy);
            accx = fmaf(sval[i + 1], f1.x, accx); accy = fmaf(sval[i + 1], f1.y, accy);
            accx = fmaf(sval[i + 2], f2.x, accx); accy = fmaf(sval[i + 2], f2.y, accy);
            accx = fmaf(sval[i + 3], f3.x, accx); accy = fmaf(sval[i + 3], f3.y, accy);
        }
        for (; i < nE; i++) {
            float2 f = __half22float2(hin[(size_t)scol[i] * 128 + tid]);
            accx = fmaf(sval[i], f.x, accx);
            accy = fmaf(sval[i], f.y, accy);
        }
    }
    size_t o = (size_t)row * HH + tid * 2;
    float2 h0v = *reinterpret_cast<const float2*>(g_h0 + o);
    float2 sv;
    sv.x = 0.8f * accx + 0.2f * h0v.x;
    sv.y = 0.8f * accy + 0.2f * h0v.y;
    *reinterpret_cast<float2*>(g_s + o) = sv;
    g_sh[(size_t)row * 128 + tid] = __floats2half2_rn(sv.x, sv.y);
}

// ---------------- fp16 mma.m16n8k16 GEMM core with ldmatrix ----------------

#define MMA_F16(ACC, A0, A1, A2, A3, B0, B1)                                 \
    asm volatile(                                                            \
        "mma.sync.aligned.m16n8k16.row.col.f32.f16.f16.f32 "                \
        "{%0,%1,%2,%3}, {%4,%5,%6,%7}, {%8,%9}, {%0,%1,%2,%3};"             \
        : "+f"((ACC)[0]), "+f"((ACC)[1]), "+f"((ACC)[2]), "+f"((ACC)[3])    \
        : "r"(A0), "r"(A1), "r"(A2), "r"(A3), "r"(B0), "r"(B1))

#define LDSM_X4(R0, R1, R2, R3, ADDR)                                        \
    asm volatile(                                                            \
        "ldmatrix.sync.aligned.m8n8.x4.shared.b16 {%0,%1,%2,%3}, [%4];"     \
        : "=r"(R0), "=r"(R1), "=r"(R2), "=r"(R3) : "r"(ADDR))

// layer GEMM: h = relu((1-beta)*s + beta*(s@W)); A = g_sh, B = g_wTh[layer]
__global__ __launch_bounds__(256, 2) void k_gemm_mma(int layer, float beta, int last) {
    __shared__ __half2 As[128][36];
    __shared__ __half2 Bs[128][36];

    const __half2* __restrict__ wTl = g_wTh + (size_t)layer * HH * 128;

    int tid = threadIdx.x;
    int wid = tid >> 5;
    int lane = tid & 31;
    int quadRow = lane >> 2;
    int quadCol = lane & 3;
    int warpM = wid >> 1;
    int warpN = wid & 1;
    int mRow = warpM * 32;
    int nBase = warpN * 64;
    int rowBase = blockIdx.x * 128;
    int colBase = blockIdx.y * 128;

    // ldmatrix lane->tile decomposition
    int lt = lane >> 3;      // tile index 0..3
    int li = lane & 7;       // row within tile

    float acc[2][8][4];
#pragma unroll
    for (int i = 0; i < 2; i++)
#pragma unroll
        for (int j = 0; j < 8; j++)
#pragma unroll
            for (int k = 0; k < 4; k++) acc[i][j][k] = 0.f;

    for (int ch = 0; ch < 4; ch++) {
        int k2 = ch * 32;
#pragma unroll
        for (int i = 0; i < 4; i++) {
            int idx = tid + i * 256;
            int r = idx >> 3;
            int c2 = (idx & 7) * 4;
            int gr = rowBase + r;
            float4 av = make_float4(0.f, 0.f, 0.f, 0.f);
            if (gr < NN)
                av = *reinterpret_cast<const float4*>(g_sh + (size_t)gr * 128 + k2 + c2);
            *reinterpret_cast<float4*>(&As[r][c2]) = av;
            *reinterpret_cast<float4*>(&Bs[r][c2]) =
                *reinterpret_cast<const float4*>(wTl + (size_t)(colBase + r) * 128 + k2 + c2);
        }
        __syncthreads();
#pragma unroll
        for (int kk2 = 0; kk2 < 32; kk2 += 8) {
            uint32_t a[2][4];
#pragma unroll
            for (int ma = 0; ma < 2; ma++) {
                // tiles: (row8, khalf) = (lt&1, lt>>1)
                uint32_t addr = (uint32_t)__cvta_generic_to_shared(
                    &As[mRow + ma * 16 + (lt & 1) * 8 + li][kk2 + (lt >> 1) * 4]);
                LDSM_X4(a[ma][0], a[ma][1], a[ma][2], a[ma][3], addr);
            }
            uint32_t b[8][2];
#pragma unroll
            for (int nb = 0; nb < 8; nb += 2) {
                // tiles: (n8 slab, khalf) = (lt>>1, lt&1)
                uint32_t addr = (uint32_t)__cvta_generic_to_shared(
                    &Bs[nBase + nb * 8 + (lt >> 1) * 8 + li][kk2 + (lt & 1) * 4]);
                uint32_t r0, r1, r2, r3;
                LDSM_X4(r0, r1, r2, r3, addr);
                b[nb][0] = r0; b[nb][1] = r1;
                b[nb + 1][0] = r2; b[nb + 1][1] = r3;
            }
#pragma unroll
            for (int nb = 0; nb < 8; nb++)
#pragma unroll
                for (int ma = 0; ma < 2; ma++)
                    MMA_F16(acc[ma][nb], a[ma][0], a[ma][1], a[ma][2], a[ma][3],
                            b[nb][0], b[nb][1]);
        }
        __syncthreads();
    }

    float omb = 1.0f - beta;
#pragma unroll
    for (int ma = 0; ma < 2; ma++) {
        int r0 = rowBase + mRow + ma * 16 + quadRow;
        int r1 = r0 + 8;
#pragma unroll
        for (int nb = 0; nb < 8; nb++) {
            int c = colBase + nBase + nb * 8 + quadCol * 2;
            if (r0 < NN) {
                float2 sv = *reinterpret_cast<const float2*>(g_s + (size_t)r0 * HH + c);
                float2 o;
                o.x = fmaxf(omb * sv.x + beta * acc[ma][nb][0], 0.f);
                o.y = fmaxf(omb * sv.y + beta * acc[ma][nb][1], 0.f);
                g_hh[(size_t)r0 * 128 + (c >> 1)] = __floats2half2_rn(o.x, o.y);
                if (last)
                    *reinterpret_cast<float2*>(g_h + (size_t)r0 * HH + c) = o;
            }
            if (r1 < NN) {
                float2 sv = *reinterpret_cast<const float2*>(g_s + (size_t)r1 * HH + c);
                float2 o;
                o.x = fmaxf(omb * sv.x + beta * acc[ma][nb][2], 0.f);
                o.y = fmaxf(omb * sv.y + beta * acc[ma][nb][3], 0.f);
                g_hh[(size_t)r1 * 128 + (c >> 1)] = __floats2half2_rn(o.x, o.y);
                if (last)
                    *reinterpret_cast<float2*>(g_h + (size_t)r1 * HH + c) = o;
            }
        }
    }
}

// projection GEMM fp16: h0 = x @ projW + b
__global__ __launch_bounds__(256, 2) void k_gemm_proj(const float* __restrict__ bias) {
    __shared__ __half2 As[128][36];
    __shared__ __half2 Bs[128][36];

    int tid = threadIdx.x;
    int wid = tid >> 5;
    int lane = tid & 31;
    int quadRow = lane >> 2;
    int quadCol = lane & 3;
    int warpM = wid >> 1;
    int warpN = wid & 1;
    int mRow = warpM * 32;
    int nBase = warpN * 64;
    int rowBase = blockIdx.x * 128;
    int colBase = blockIdx.y * 128;

    int lt = lane >> 3;
    int li = lane & 7;

    float acc[2][8][4];
#pragma unroll
    for (int i = 0; i < 2; i++)
#pragma unroll
        for (int j = 0; j < 8; j++)
#pragma unroll
            for (int k = 0; k < 4; k++) acc[i][j][k] = 0.f;

    for (int ch = 0; ch < 16; ch++) {
        int k2 = ch * 32;
#pragma unroll
        for (int i = 0; i < 4; i++) {
            int idx = tid + i * 256;
            int r = idx >> 3;
            int c2 = (idx & 7) * 4;
            int gr = rowBase + r;
            float4 av = make_float4(0.f, 0.f, 0.f, 0.f);
            if (gr < NN)
                av = *reinterpret_cast<const float4*>(g_xh + (size_t)gr * 512 + k2 + c2);
            *reinterpret_cast<float4*>(&As[r][c2]) = av;
            *reinterpret_cast<float4*>(&Bs[r][c2]) =
                *reinterpret_cast<const float4*>(g_pWh + (size_t)(colBase + r) * 512 + k2 + c2);
        }
        __syncthreads();
#pragma unroll
        for (int kk2 = 0; kk2 < 32; kk2 += 8) {
            uint32_t a[2][4];
#pragma unroll
            for (int ma = 0; ma < 2; ma++) {
                uint32_t addr = (uint32_t)__cvta_generic_to_shared(
                    &As[mRow + ma * 16 + (lt & 1) * 8 + li][kk2 + (lt >> 1) * 4]);
                LDSM_X4(a[ma][0], a[ma][1], a[ma][2], a[ma][3], addr);
            }
            uint32_t b[8][2];
#pragma unroll
            for (int nb = 0; nb < 8; nb += 2) {
                uint32_t addr = (uint32_t)__cvta_generic_to_shared(
                    &Bs[nBase + nb * 8 + (lt >> 1) * 8 + li][kk2 + (lt & 1) * 4]);
                uint32_t r0, r1, r2, r3;
                LDSM_X4(r0, r1, r2, r3, addr);
                b[nb][0] = r0; b[nb][1] = r1;
                b[nb + 1][0] = r2; b[nb + 1][1] = r3;
            }
#pragma unroll
            for (int nb = 0; nb < 8; nb++)
#pragma unroll
                for (int ma = 0; ma < 2; ma++)
                    MMA_F16(acc[ma][nb], a[ma][0], a[ma][1], a[ma][2], a[ma][3],
                            b[nb][0], b[nb][1]);
        }
        __syncthreads();
    }

#pragma unroll
    for (int ma = 0; ma < 2; ma++) {
        int r0 = rowBase + mRow + ma * 16 + quadRow;
        int r1 = r0 + 8;
#pragma unroll
        for (int nb = 0; nb < 8; nb++) {
            int c = colBase + nBase + nb * 8 + quadCol * 2;
            float bx = bias[c], by = bias[c + 1];
            if (r0 < NN) {
                float vx = acc[ma][nb][0] + bx;
                float vy = acc[ma][nb][1] + by;
                *reinterpret_cast<float2*>(g_h0 + (size_t)r0 * HH + c) = make_float2(vx, vy);
                g_h0h[(size_t)r0 * 128 + (c >> 1)] = __floats2half2_rn(vx, vy);
            }
            if (r1 < NN) {
                float vx = acc[ma][nb][2] + bx;
                float vy = acc[ma][nb][3] + by;
                *reinterpret_cast<float2*>(g_h0 + (size_t)r1 * HH + c) = make_float2(vx, vy);
                g_h0h[(size_t)r1 * 128 + (c >> 1)] = __floats2half2_rn(vx, vy);
            }
        }
    }
}

// ---------------- classifier ----------------
__global__ void k_cls(const float* __restrict__ Wc, const float* __restrict__ bc,
                      float* __restrict__ out) {
    int gw   = (blockIdx.x * blockDim.x + threadIdx.x) >> 5;
    int lane = threadIdx.x & 31;
    if (gw >= NN) return;
    const float* hr = g_h + (size_t)gw * HH;
    float a0 = 0.f, a1 = 0.f, a2 = 0.f, a3 = 0.f;
    for (int k = lane; k < HH; k += 32) {
        float hv = hr[k];
        const float* w = Wc + k * CC;
        a0 = fmaf(hv, w[0], a0);
        a1 = fmaf(hv, w[1], a1);
        a2 = fmaf(hv, w[2], a2);
        a3 = fmaf(hv, w[3], a3);
    }
#pragma unroll
    for (int off = 16; off; off >>= 1) {
        a0 += __shfl_down_sync(0xffffffffu, a0, off);
        a1 += __shfl_down_sync(0xffffffffu, a1, off);
        a2 += __shfl_down_sync(0xffffffffu, a2, off);
        a3 += __shfl_down_sync(0xffffffffu, a3, off);
    }
    if (lane == 0) {
        out[gw * CC + 0] = a0 + bc[0];
        out[gw * CC + 1] = a1 + bc[1];
        out[gw * CC + 2] = a2 + bc[2];
        out[gw * CC + 3] = a3 + bc[3];
    }
}

// ---------------- launch ----------------

extern "C" void kernel_launch(void* const* d_in, const int* in_sizes, int n_in,
                              void* d_out, int out_size) {
    const float* x     = (const float*)d_in[0];
    const int*   ei    = (const int*)  d_in[1];
    const float* projW = (const float*)d_in[2];
    const float* projb = (const float*)d_in[3];
    const float* wts   = (const float*)d_in[4];
    const float* clsW  = (const float*)d_in[5];
    const float* clsb  = (const float*)d_in[6];
    float* out = (float*)d_out;

    const int* src = ei;
    const int* dst = ei + EE;

    k_init_deg<<<(NN + 255) / 256, 256>>>();
    k_count   <<<(EE + 255) / 256, 256>>>(dst);
    k_dinv    <<<(NN + 255) / 256, 256>>>();
    k_scan    <<<1, 1024>>>();
    k_selfloop<<<(NN + 255) / 256, 256>>>();
    k_fill    <<<(EE + 255) / 256, 256>>>(src, dst);

    dim3 tg(HH / 32, HH / 32, LL);
    k_transpose_w<<<tg, dim3(32, 8)>>>(wts);
    dim3 pg(HH / 32, DIN / 32);
    k_transpose_pw<<<pg, dim3(32, 8)>>>(projW);
    k_x2h<<<(NN * DIN / 4 + 255) / 256, 256>>>(x);

    dim3 gg((NN + 127) / 128, 2);
    k_gemm_proj<<<gg, 256>>>(projb);

    dim3 mg((NN + 127) / 128, HH / 128);
    for (int l = 0; l < LL; l++) {
        k_spmm<<<NN, 128>>>(l == 0 ? 1 : 0);
        float beta = logf(0.5f / (float)(l + 1) + 1.0f);
        k_gemm_mma<<<mg, 256>>>(l, beta, l == LL - 1 ? 1 : 0);
    }

    k_cls<<<(NN * 32 + 255) / 256, 256>>>(clsW, clsb, out);
}

// round 11
// speedup vs baseline: 2.8372x; 1.2203x over previous
#include <cuda_runtime.h>
#include <cuda_fp16.h>
#include <math.h>
#include <stdint.h>

#define NN   50000
#define EE   1600000
#define DIN  1024
#define HH   256
#define LL   64
#define CC   4
#define NNZ  (EE + NN)

// ---------------- scratch (device globals: no allocation allowed) ----------
__device__ float   g_h0[(size_t)NN * HH];           // fp32 h0 (residual anchor)
__device__ __half2 g_hh [(size_t)NN * (HH / 2)];    // fp16 h   (SpMM gather / cls input)
__device__ __half2 g_h0h[(size_t)NN * (HH / 2)];    // fp16 h0
__device__ __half2 g_sh [(size_t)NN * (HH / 2)];    // fp16 s   (layer-GEMM A operand)
__device__ __half2 g_xh [(size_t)NN * (DIN / 2)];   // fp16 x
__device__ __half2 g_wTh[(size_t)LL * HH * (HH / 2)];  // fp16 W'^T = ((1-b)I + b W)^T
__device__ __half2 g_pWh[(size_t)HH * (DIN / 2)];
__device__ int     g_deg[NN];
__device__ float   g_dinv[NN];
__device__ int     g_rowptr[NN + 1];
__device__ int     g_fill[NN];
__device__ int     g_col[NNZ];
__device__ float   g_val[NNZ];

// ---------------- graph preprocessing ----------------

__global__ void k_init_deg() {
    int i = blockIdx.x * blockDim.x + threadIdx.x;
    if (i < NN) g_deg[i] = 1;
}
__global__ void k_count(const int* __restrict__ dst) {
    int e = blockIdx.x * blockDim.x + threadIdx.x;
    if (e < EE) atomicAdd(&g_deg[dst[e]], 1);
}
__global__ void k_dinv() {
    int i = blockIdx.x * blockDim.x + threadIdx.x;
    if (i < NN) g_dinv[i] = rsqrtf((float)g_deg[i]);
}
__global__ void k_scan() {
    __shared__ int sh[1024];
    __shared__ int carry;
    int tid = threadIdx.x;
    if (tid == 0) { carry = 0; g_rowptr[0] = 0; }
    __syncthreads();
    for (int base = 0; base < NN; base += 1024) {
        int i = base + tid;
        int v = (i < NN) ? g_deg[i] : 0;
        sh[tid] = v;
        __syncthreads();
        for (int off = 1; off < 1024; off <<= 1) {
            int t = (tid >= off) ? sh[tid - off] : 0;
            __syncthreads();
            sh[tid] += t;
            __syncthreads();
        }
        if (i < NN) g_rowptr[i + 1] = carry + sh[tid];
        __syncthreads();
        if (tid == 0) carry += sh[1023];
        __syncthreads();
    }
}
__global__ void k_selfloop() {
    int i = blockIdx.x * blockDim.x + threadIdx.x;
    if (i < NN) {
        int p = g_rowptr[i];
        float d = g_dinv[i];
        g_col[p] = i;
        g_val[p] = d * d;
        g_fill[i] = 1;
    }
}
__global__ void k_fill(const int* __restrict__ src, const int* __restrict__ dst) {
    int e = blockIdx.x * blockDim.x + threadIdx.x;
    if (e < EE) {
        int d = dst[e];
        int s = src[e];
        int p = atomicAdd(&g_fill[d], 1);
        int idx = g_rowptr[d] + p;
        g_col[idx] = s;
        g_val[idx] = g_dinv[s] * g_dinv[d];
    }
}

// weight transpose + residual fold: g_wTh[l][n][k] = fp16((1-b)I[k][n] + b*W[l][k][n])
__global__ void k_transpose_w(const float* __restrict__ W) {
    __shared__ float t[32][33];
    int l = blockIdx.z;
    float beta = logf(0.5f / (float)(l + 1) + 1.0f);
    int n0 = blockIdx.x * 32, k0 = blockIdx.y * 32;
    const float* Wl = W + (size_t)l * HH * HH;
    __half* out = reinterpret_cast<__half*>(g_wTh) + (size_t)l * HH * HH;
#pragma unroll
    for (int dy = 0; dy < 32; dy += 8)
        t[threadIdx.y + dy][threadIdx.x] = Wl[(size_t)(k0 + threadIdx.y + dy) * HH + n0 + threadIdx.x];
    __syncthreads();
#pragma unroll
    for (int dy = 0; dy < 32; dy += 8) {
        int n = n0 + threadIdx.y + dy;
        int k = k0 + threadIdx.x;
        float v = beta * t[threadIdx.x][threadIdx.y + dy];
        if (n == k) v += 1.0f - beta;
        out[(size_t)n * HH + k] = __float2half_rn(v);
    }
}

// projW transpose to fp16: g_pWh[n][k] = (half)projW[k][n]
__global__ void k_transpose_pw(const float* __restrict__ PW) {
    __shared__ float t[32][33];
    int n0 = blockIdx.x * 32, k0 = blockIdx.y * 32;
    __half* out = reinterpret_cast<__half*>(g_pWh);
#pragma unroll
    for (int dy = 0; dy < 32; dy += 8)
        t[threadIdx.y + dy][threadIdx.x] = PW[(size_t)(k0 + threadIdx.y + dy) * HH + n0 + threadIdx.x];
    __syncthreads();
#pragma unroll
    for (int dy = 0; dy < 32; dy += 8)
        out[(size_t)(n0 + threadIdx.y + dy) * DIN + k0 + threadIdx.x] =
            __float2half_rn(t[threadIdx.x][threadIdx.y + dy]);
}

// x -> fp16
__global__ void k_x2h(const float* __restrict__ x) {
    int i = blockIdx.x * blockDim.x + threadIdx.x;
    const int total = NN * DIN / 4;
    if (i < total) {
        float4 v = reinterpret_cast<const float4*>(x)[i];
        g_xh[i * 2 + 0] = __floats2half2_rn(v.x, v.y);
        g_xh[i * 2 + 1] = __floats2half2_rn(v.z, v.w);
    }
}

// ---------------- SpMM: s_fp16 = 0.8 * (A_hat @ h_fp16) + 0.2 * h0_fp32 -----
__global__ __launch_bounds__(128) void k_spmm(int first) {
    const __half2* __restrict__ hin = first ? g_h0h : g_hh;
    int row = blockIdx.x;
    int tid = threadIdx.x;
    int s0 = g_rowptr[row];
    int s1 = g_rowptr[row + 1];
    __shared__ int   scol[64];
    __shared__ float sval[64];
    float accx = 0.f, accy = 0.f;
    for (int e0 = s0; e0 < s1; e0 += 64) {
        int nE = min(64, s1 - e0);
        __syncthreads();
        if (tid < nE) { scol[tid] = g_col[e0 + tid]; sval[tid] = g_val[e0 + tid]; }
        __syncthreads();
        int i = 0;
        for (; i + 4 <= nE; i += 4) {
            float2 f0 = __half22float2(hin[(size_t)scol[i + 0] * 128 + tid]);
            float2 f1 = __half22float2(hin[(size_t)scol[i + 1] * 128 + tid]);
            float2 f2 = __half22float2(hin[(size_t)scol[i + 2] * 128 + tid]);
            float2 f3 = __half22float2(hin[(size_t)scol[i + 3] * 128 + tid]);
            accx = fmaf(sval[i + 0], f0.x, accx); accy = fmaf(sval[i + 0], f0.y, accy);
            accx = fmaf(sval[i + 1], f1.x, accx); accy = fmaf(sval[i + 1], f1.y, accy);
            accx = fmaf(sval[i + 2], f2.x, accx); accy = fmaf(sval[i + 2], f2.y, accy);
            accx = fmaf(sval[i + 3], f3.x, accx); accy = fmaf(sval[i + 3], f3.y, accy);
        }
        for (; i < nE; i++) {
            float2 f = __half22float2(hin[(size_t)scol[i] * 128 + tid]);
            accx = fmaf(sval[i], f.x, accx);
            accy = fmaf(sval[i], f.y, accy);
        }
    }
    size_t o = (size_t)row * HH + tid * 2;
    float2 h0v = *reinterpret_cast<const float2*>(g_h0 + o);
    g_sh[(size_t)row * 128 + tid] =
        __floats2half2_rn(0.8f * accx + 0.2f * h0v.x, 0.8f * accy + 0.2f * h0v.y);
}

// ---------------- fp16 mma.m16n8k16 GEMM core with ldmatrix ----------------

#define MMA_F16(ACC, A0, A1, A2, A3, B0, B1)                                 \
    asm volatile(                                                            \
        "mma.sync.aligned.m16n8k16.row.col.f32.f16.f16.f32 "                \
        "{%0,%1,%2,%3}, {%4,%5,%6,%7}, {%8,%9}, {%0,%1,%2,%3};"             \
        : "+f"((ACC)[0]), "+f"((ACC)[1]), "+f"((ACC)[2]), "+f"((ACC)[3])    \
        : "r"(A0), "r"(A1), "r"(A2), "r"(A3), "r"(B0), "r"(B1))

#define LDSM_X4(R0, R1, R2, R3, ADDR)                                        \
    asm volatile(                                                            \
        "ldmatrix.sync.aligned.m8n8.x4.shared.b16 {%0,%1,%2,%3}, [%4];"     \
        : "=r"(R0), "=r"(R1), "=r"(R2), "=r"(R3) : "r"(ADDR))

// layer GEMM: h = relu(s @ W'); A = g_sh, B = g_wTh[layer] (residual folded)
__global__ __launch_bounds__(256, 2) void k_gemm_mma(int layer) {
    __shared__ __half2 As[128][36];
    __shared__ __half2 Bs[128][36];

    const __half2* __restrict__ wTl = g_wTh + (size_t)layer * HH * 128;

    int tid = threadIdx.x;
    int wid = tid >> 5;
    int lane = tid & 31;
    int quadRow = lane >> 2;
    int quadCol = lane & 3;
    int warpM = wid >> 1;
    int warpN = wid & 1;
    int mRow = warpM * 32;
    int nBase = warpN * 64;
    int rowBase = blockIdx.x * 128;
    int colBase = blockIdx.y * 128;

    int lt = lane >> 3;
    int li = lane & 7;

    float acc[2][8][4];
#pragma unroll
    for (int i = 0; i < 2; i++)
#pragma unroll
        for (int j = 0; j < 8; j++)
#pragma unroll
            for (int k = 0; k < 4; k++) acc[i][j][k] = 0.f;

    for (int ch = 0; ch < 4; ch++) {
        int k2 = ch * 32;
#pragma unroll
        for (int i = 0; i < 4; i++) {
            int idx = tid + i * 256;
            int r = idx >> 3;
            int c2 = (idx & 7) * 4;
            int gr = rowBase + r;
            float4 av = make_float4(0.f, 0.f, 0.f, 0.f);
            if (gr < NN)
                av = *reinterpret_cast<const float4*>(g_sh + (size_t)gr * 128 + k2 + c2);
            *reinterpret_cast<float4*>(&As[r][c2]) = av;
            *reinterpret_cast<float4*>(&Bs[r][c2]) =
                *reinterpret_cast<const float4*>(wTl + (size_t)(colBase + r) * 128 + k2 + c2);
        }
        __syncthreads();
#pragma unroll
        for (int kk2 = 0; kk2 < 32; kk2 += 8) {
            uint32_t a[2][4];
#pragma unroll
            for (int ma = 0; ma < 2; ma++) {
                uint32_t addr = (uint32_t)__cvta_generic_to_shared(
                    &As[mRow + ma * 16 + (lt & 1) * 8 + li][kk2 + (lt >> 1) * 4]);
                LDSM_X4(a[ma][0], a[ma][1], a[ma][2], a[ma][3], addr);
            }
            uint32_t b[8][2];
#pragma unroll
            for (int nb = 0; nb < 8; nb += 2) {
                uint32_t addr = (uint32_t)__cvta_generic_to_shared(
                    &Bs[nBase + nb * 8 + (lt >> 1) * 8 + li][kk2 + (lt & 1) * 4]);
                uint32_t r0, r1, r2, r3;
                LDSM_X4(r0, r1, r2, r3, addr);
                b[nb][0] = r0; b[nb][1] = r1;
                b[nb + 1][0] = r2; b[nb + 1][1] = r3;
            }
#pragma unroll
            for (int nb = 0; nb < 8; nb++)
#pragma unroll
                for (int ma = 0; ma < 2; ma++)
                    MMA_F16(acc[ma][nb], a[ma][0], a[ma][1], a[ma][2], a[ma][3],
                            b[nb][0], b[nb][1]);
        }
        __syncthreads();
    }

    // epilogue: h = relu(acc) -> fp16 only
#pragma unroll
    for (int ma = 0; ma < 2; ma++) {
        int r0 = rowBase + mRow + ma * 16 + quadRow;
        int r1 = r0 + 8;
#pragma unroll
        for (int nb = 0; nb < 8; nb++) {
            int c = colBase + nBase + nb * 8 + quadCol * 2;
            if (r0 < NN)
                g_hh[(size_t)r0 * 128 + (c >> 1)] = __floats2half2_rn(
                    fmaxf(acc[ma][nb][0], 0.f), fmaxf(acc[ma][nb][1], 0.f));
            if (r1 < NN)
                g_hh[(size_t)r1 * 128 + (c >> 1)] = __floats2half2_rn(
                    fmaxf(acc[ma][nb][2], 0.f), fmaxf(acc[ma][nb][3], 0.f));
        }
    }
}

// projection GEMM fp16: h0 = x @ projW + b
__global__ __launch_bounds__(256, 2) void k_gemm_proj(const float* __restrict__ bias) {
    __shared__ __half2 As[128][36];
    __shared__ __half2 Bs[128][36];

    int tid = threadIdx.x;
    int wid = tid >> 5;
    int lane = tid & 31;
    int quadRow = lane >> 2;
    int quadCol = lane & 3;
    int warpM = wid >> 1;
    int warpN = wid & 1;
    int mRow = warpM * 32;
    int nBase = warpN * 64;
    int rowBase = blockIdx.x * 128;
    int colBase = blockIdx.y * 128;

    int lt = lane >> 3;
    int li = lane & 7;

    float acc[2][8][4];
#pragma unroll
    for (int i = 0; i < 2; i++)
#pragma unroll
        for (int j = 0; j < 8; j++)
#pragma unroll
            for (int k = 0; k < 4; k++) acc[i][j][k] = 0.f;

    for (int ch = 0; ch < 16; ch++) {
        int k2 = ch * 32;
#pragma unroll
        for (int i = 0; i < 4; i++) {
            int idx = tid + i * 256;
            int r = idx >> 3;
            int c2 = (idx & 7) * 4;
            int gr = rowBase + r;
            float4 av = make_float4(0.f, 0.f, 0.f, 0.f);
            if (gr < NN)
                av = *reinterpret_cast<const float4*>(g_xh + (size_t)gr * 512 + k2 + c2);
            *reinterpret_cast<float4*>(&As[r][c2]) = av;
            *reinterpret_cast<float4*>(&Bs[r][c2]) =
                *reinterpret_cast<const float4*>(g_pWh + (size_t)(colBase + r) * 512 + k2 + c2);
        }
        __syncthreads();
#pragma unroll
        for (int kk2 = 0; kk2 < 32; kk2 += 8) {
            uint32_t a[2][4];
#pragma unroll
            for (int ma = 0; ma < 2; ma++) {
                uint32_t addr = (uint32_t)__cvta_generic_to_shared(
                    &As[mRow + ma * 16 + (lt & 1) * 8 + li][kk2 + (lt >> 1) * 4]);
                LDSM_X4(a[ma][0], a[ma][1], a[ma][2], a[ma][3], addr);
            }
            uint32_t b[8][2];
#pragma unroll
            for (int nb = 0; nb < 8; nb += 2) {
                uint32_t addr = (uint32_t)__cvta_generic_to_shared(
                    &Bs[nBase + nb * 8 + (lt >> 1) * 8 + li][kk2 + (lt & 1) * 4]);
                uint32_t r0, r1, r2, r3;
                LDSM_X4(r0, r1, r2, r3, addr);
                b[nb][0] = r0; b[nb][1] = r1;
                b[nb + 1][0] = r2; b[nb + 1][1] = r3;
            }
#pragma unroll
            for (int nb = 0; nb < 8; nb++)
#pragma unroll
                for (int ma = 0; ma < 2; ma++)
                    MMA_F16(acc[ma][nb], a[ma][0], a[ma][1], a[ma][2], a[ma][3],
                            b[nb][0], b[nb][1]);
        }
        __syncthreads();
    }

#pragma unroll
    for (int ma = 0; ma < 2; ma++) {
        int r0 = rowBase + mRow + ma * 16 + quadRow;
        int r1 = r0 + 8;
#pragma unroll
        for (int nb = 0; nb < 8; nb++) {
            int c = colBase + nBase + nb * 8 + quadCol * 2;
            float bx = bias[c], by = bias[c + 1];
            if (r0 < NN) {
                float vx = acc[ma][nb][0] + bx;
                float vy = acc[ma][nb][1] + by;
                *reinterpret_cast<float2*>(g_h0 + (size_t)r0 * HH + c) = make_float2(vx, vy);
                g_h0h[(size_t)r0 * 128 + (c >> 1)] = __floats2half2_rn(vx, vy);
            }
            if (r1 < NN) {
                float vx = acc[ma][nb][2] + bx;
                float vy = acc[ma][nb][3] + by;
                *reinterpret_cast<float2*>(g_h0 + (size_t)r1 * HH + c) = make_float2(vx, vy);
                g_h0h[(size_t)r1 * 128 + (c >> 1)] = __floats2half2_rn(vx, vy);
            }
        }
    }
}

// ---------------- classifier (reads fp16 h) ----------------
__global__ void k_cls(const float* __restrict__ Wc, const float* __restrict__ bc,
                      float* __restrict__ out) {
    int gw   = (blockIdx.x * blockDim.x + threadIdx.x) >> 5;
    int lane = threadIdx.x & 31;
    if (gw >= NN) return;
    const __half2* hr = g_hh + (size_t)gw * 128;
    float a0 = 0.f, a1 = 0.f, a2 = 0.f, a3 = 0.f;
    for (int k2 = lane; k2 < 128; k2 += 32) {
        float2 hv = __half22float2(hr[k2]);
        const float* w0 = Wc + (k2 * 2) * CC;
        a0 = fmaf(hv.x, w0[0], a0); a1 = fmaf(hv.x, w0[1], a1);
        a2 = fmaf(hv.x, w0[2], a2); a3 = fmaf(hv.x, w0[3], a3);
        a0 = fmaf(hv.y, w0[4], a0); a1 = fmaf(hv.y, w0[5], a1);
        a2 = fmaf(hv.y, w0[6], a2); a3 = fmaf(hv.y, w0[7], a3);
    }
#pragma unroll
    for (int off = 16; off; off >>= 1) {
        a0 += __shfl_down_sync(0xffffffffu, a0, off);
        a1 += __shfl_down_sync(0xffffffffu, a1, off);
        a2 += __shfl_down_sync(0xffffffffu, a2, off);
        a3 += __shfl_down_sync(0xffffffffu, a3, off);
    }
    if (lane == 0) {
        out[gw * CC + 0] = a0 + bc[0];
        out[gw * CC + 1] = a1 + bc[1];
        out[gw * CC + 2] = a2 + bc[2];
        out[gw * CC + 3] = a3 + bc[3];
    }
}

// ---------------- launch ----------------

extern "C" void kernel_launch(void* const* d_in, const int* in_sizes, int n_in,
                              void* d_out, int out_size) {
    const float* x     = (const float*)d_in[0];
    const int*   ei    = (const int*)  d_in[1];
    const float* projW = (const float*)d_in[2];
    const float* projb = (const float*)d_in[3];
    const float* wts   = (const float*)d_in[4];
    const float* clsW  = (const float*)d_in[5];
    const float* clsb  = (const float*)d_in[6];
    float* out = (float*)d_out;

    const int* src = ei;
    const int* dst = ei + EE;

    k_init_deg<<<(NN + 255) / 256, 256>>>();
    k_count   <<<(EE + 255) / 256, 256>>>(dst);
    k_dinv    <<<(NN + 255) / 256, 256>>>();
    k_scan    <<<1, 1024>>>();
    k_selfloop<<<(NN + 255) / 256, 256>>>();
    k_fill    <<<(EE + 255) / 256, 256>>>(src, dst);

    dim3 tg(HH / 32, HH / 32, LL);
    k_transpose_w<<<tg, dim3(32, 8)>>>(wts);
    dim3 pg(HH / 32, DIN / 32);
    k_transpose_pw<<<pg, dim3(32, 8)>>>(projW);
    k_x2h<<<(NN * DIN / 4 + 255) / 256, 256>>>(x);

    dim3 gg((NN + 127) / 128, 2);
    k_gemm_proj<<<gg, 256>>>(projb);

    dim3 mg((NN + 127) / 128, HH / 128);
    for (int l = 0; l < LL; l++) {
        k_spmm<<<NN, 128>>>(l == 0 ? 1 : 0);
        k_gemm_mma<<<mg, 256>>>(l);
    }

    k_cls<<<(NN * 32 + 255) / 256, 256>>>(clsW, clsb, out);
}

// round 12
// speedup vs baseline: 2.9732x; 1.0479x over previous
#include <cuda_runtime.h>
#include <cuda_fp16.h>
#include <math.h>
#include <stdint.h>

#define NN   50000
#define EE   1600000
#define DIN  1024
#define HH   256
#define LL   64
#define CC   4
#define NNZ  (EE + NN)

// ---------------- scratch (device globals: no allocation allowed) ----------
__device__ __half2 g_hh [(size_t)NN * (HH / 2)];    // fp16 h
__device__ __half2 g_h0h[(size_t)NN * (HH / 2)];    // fp16 h0
__device__ __half2 g_sh [(size_t)NN * (HH / 2)];    // fp16 s
__device__ __half2 g_xh [(size_t)NN * (DIN / 2)];   // fp16 x
__device__ __half2 g_wTh[(size_t)LL * HH * (HH / 2)];  // fp16 W'^T = ((1-b)I + b W)^T
__device__ __half2 g_pWh[(size_t)HH * (DIN / 2)];
__device__ int     g_deg[NN];
__device__ float   g_dinv[NN];
__device__ int     g_rowptr[NN + 1];
__device__ int     g_fill[NN];
__device__ int     g_col[NNZ];
__device__ float   g_val[NNZ];

// ---------------- graph preprocessing ----------------

__global__ void k_init_deg() {
    int i = blockIdx.x * blockDim.x + threadIdx.x;
    if (i < NN) g_deg[i] = 1;
}
__global__ void k_count(const int* __restrict__ dst) {
    int e = blockIdx.x * blockDim.x + threadIdx.x;
    if (e < EE) atomicAdd(&g_deg[dst[e]], 1);
}
__global__ void k_dinv() {
    int i = blockIdx.x * blockDim.x + threadIdx.x;
    if (i < NN) g_dinv[i] = rsqrtf((float)g_deg[i]);
}
__global__ void k_scan() {
    __shared__ int sh[1024];
    __shared__ int carry;
    int tid = threadIdx.x;
    if (tid == 0) { carry = 0; g_rowptr[0] = 0; }
    __syncthreads();
    for (int base = 0; base < NN; base += 1024) {
        int i = base + tid;
        int v = (i < NN) ? g_deg[i] : 0;
        sh[tid] = v;
        __syncthreads();
        for (int off = 1; off < 1024; off <<= 1) {
            int t = (tid >= off) ? sh[tid - off] : 0;
            __syncthreads();
            sh[tid] += t;
            __syncthreads();
        }
        if (i < NN) g_rowptr[i + 1] = carry + sh[tid];
        __syncthreads();
        if (tid == 0) carry += sh[1023];
        __syncthreads();
    }
}
__global__ void k_selfloop() {
    int i = blockIdx.x * blockDim.x + threadIdx.x;
    if (i < NN) {
        int p = g_rowptr[i];
        float d = g_dinv[i];
        g_col[p] = i;
        g_val[p] = d * d;
        g_fill[i] = 1;
    }
}
__global__ void k_fill(const int* __restrict__ src, const int* __restrict__ dst) {
    int e = blockIdx.x * blockDim.x + threadIdx.x;
    if (e < EE) {
        int d = dst[e];
        int s = src[e];
        int p = atomicAdd(&g_fill[d], 1);
        int idx = g_rowptr[d] + p;
        g_col[idx] = s;
        g_val[idx] = g_dinv[s] * g_dinv[d];
    }
}

// weight transpose + residual fold: g_wTh[l][n][k] = fp16((1-b)I[k][n] + b*W[l][k][n])
__global__ void k_transpose_w(const float* __restrict__ W) {
    __shared__ float t[32][33];
    int l = blockIdx.z;
    float beta = logf(0.5f / (float)(l + 1) + 1.0f);
    int n0 = blockIdx.x * 32, k0 = blockIdx.y * 32;
    const float* Wl = W + (size_t)l * HH * HH;
    __half* out = reinterpret_cast<__half*>(g_wTh) + (size_t)l * HH * HH;
#pragma unroll
    for (int dy = 0; dy < 32; dy += 8)
        t[threadIdx.y + dy][threadIdx.x] = Wl[(size_t)(k0 + threadIdx.y + dy) * HH + n0 + threadIdx.x];
    __syncthreads();
#pragma unroll
    for (int dy = 0; dy < 32; dy += 8) {
        int n = n0 + threadIdx.y + dy;
        int k = k0 + threadIdx.x;
        float v = beta * t[threadIdx.x][threadIdx.y + dy];
        if (n == k) v += 1.0f - beta;
        out[(size_t)n * HH + k] = __float2half_rn(v);
    }
}

// projW transpose to fp16: g_pWh[n][k] = (half)projW[k][n]
__global__ void k_transpose_pw(const float* __restrict__ PW) {
    __shared__ float t[32][33];
    int n0 = blockIdx.x * 32, k0 = blockIdx.y * 32;
    __half* out = reinterpret_cast<__half*>(g_pWh);
#pragma unroll
    for (int dy = 0; dy < 32; dy += 8)
        t[threadIdx.y + dy][threadIdx.x] = PW[(size_t)(k0 + threadIdx.y + dy) * HH + n0 + threadIdx.x];
    __syncthreads();
#pragma unroll
    for (int dy = 0; dy < 32; dy += 8)
        out[(size_t)(n0 + threadIdx.y + dy) * DIN + k0 + threadIdx.x] =
            __float2half_rn(t[threadIdx.x][threadIdx.y + dy]);
}

// x -> fp16
__global__ void k_x2h(const float* __restrict__ x) {
    int i = blockIdx.x * blockDim.x + threadIdx.x;
    const int total = NN * DIN / 4;
    if (i < total) {
        float4 v = reinterpret_cast<const float4*>(x)[i];
        g_xh[i * 2 + 0] = __floats2half2_rn(v.x, v.y);
        g_xh[i * 2 + 1] = __floats2half2_rn(v.z, v.w);
    }
}

// ---------------- SpMM: s_fp16 = 0.8 * (A_hat @ h) + 0.2 * h0 (all fp16) ----
__global__ __launch_bounds__(128) void k_spmm(int first) {
    const __half2* __restrict__ hin = first ? g_h0h : g_hh;
    int row = blockIdx.x;
    int tid = threadIdx.x;
    int s0 = g_rowptr[row];
    int s1 = g_rowptr[row + 1];
    __shared__ int   scol[64];
    __shared__ float sval[64];
    float accx = 0.f, accy = 0.f;
    for (int e0 = s0; e0 < s1; e0 += 64) {
        int nE = min(64, s1 - e0);
        __syncthreads();
        if (tid < nE) { scol[tid] = g_col[e0 + tid]; sval[tid] = g_val[e0 + tid]; }
        __syncthreads();
        int i = 0;
        for (; i + 4 <= nE; i += 4) {
            float2 f0 = __half22float2(hin[(size_t)scol[i + 0] * 128 + tid]);
            float2 f1 = __half22float2(hin[(size_t)scol[i + 1] * 128 + tid]);
            float2 f2 = __half22float2(hin[(size_t)scol[i + 2] * 128 + tid]);
            float2 f3 = __half22float2(hin[(size_t)scol[i + 3] * 128 + tid]);
            accx = fmaf(sval[i + 0], f0.x, accx); accy = fmaf(sval[i + 0], f0.y, accy);
            accx = fmaf(sval[i + 1], f1.x, accx); accy = fmaf(sval[i + 1], f1.y, accy);
            accx = fmaf(sval[i + 2], f2.x, accx); accy = fmaf(sval[i + 2], f2.y, accy);
            accx = fmaf(sval[i + 3], f3.x, accx); accy = fmaf(sval[i + 3], f3.y, accy);
        }
        for (; i < nE; i++) {
            float2 f = __half22float2(hin[(size_t)scol[i] * 128 + tid]);
            accx = fmaf(sval[i], f.x, accx);
            accy = fmaf(sval[i], f.y, accy);
        }
    }
    float2 h0v = __half22float2(g_h0h[(size_t)row * 128 + tid]);
    g_sh[(size_t)row * 128 + tid] =
        __floats2half2_rn(0.8f * accx + 0.2f * h0v.x, 0.8f * accy + 0.2f * h0v.y);
}

// ---------------- fp16 mma.m16n8k16 pipelined GEMM core ----------------

#define MMA_F16(ACC, A0, A1, A2, A3, B0, B1)                                 \
    asm volatile(                                                            \
        "mma.sync.aligned.m16n8k16.row.col.f32.f16.f16.f32 "                \
        "{%0,%1,%2,%3}, {%4,%5,%6,%7}, {%8,%9}, {%0,%1,%2,%3};"             \
        : "+f"((ACC)[0]), "+f"((ACC)[1]), "+f"((ACC)[2]), "+f"((ACC)[3])    \
        : "r"(A0), "r"(A1), "r"(A2), "r"(A3), "r"(B0), "r"(B1))

#define LDSM_X4(R0, R1, R2, R3, ADDR)                                        \
    asm volatile(                                                            \
        "ldmatrix.sync.aligned.m8n8.x4.shared.b16 {%0,%1,%2,%3}, [%4];"     \
        : "=r"(R0), "=r"(R1), "=r"(R2), "=r"(R3) : "r"(ADDR))

__device__ __forceinline__ void cp_async16(uint32_t saddr, const void* g, int srcBytes) {
    asm volatile("cp.async.ca.shared.global [%0], [%1], 16, %2;"
                 :: "r"(saddr), "l"(g), "r"(srcBytes) : "memory");
}
#define CP_COMMIT() asm volatile("cp.async.commit_group;" ::: "memory")
#define CP_WAIT0()  asm volatile("cp.async.wait_group 0;" ::: "memory")

#define TPAD 36
#define STAGE_H2 (128 * TPAD)            // h2 per stage buffer
#define GEMM_SMEM (4 * STAGE_H2 * 4)     // 2 A stages + 2 B stages, bytes = 73728

// layer GEMM: h = relu(s @ W'); pipelined, 4 K-chunks of 32 h2
__global__ __launch_bounds__(256, 2) void k_gemm_mma(int layer) {
    extern __shared__ __half2 dsm[];
    __half2* Abuf[2] = { dsm, dsm + STAGE_H2 };
    __half2* Bbuf[2] = { dsm + 2 * STAGE_H2, dsm + 3 * STAGE_H2 };

    const __half2* __restrict__ wTl = g_wTh + (size_t)layer * HH * 128;

    int tid = threadIdx.x;
    int wid = tid >> 5;
    int lane = tid & 31;
    int quadRow = lane >> 2;
    int quadCol = lane & 3;
    int warpM = wid >> 1;
    int warpN = wid & 1;
    int mRow = warpM * 32;
    int nBase = warpN * 64;
    int rowBase = blockIdx.x * 128;
    int colBase = blockIdx.y * 128;

    int lt = lane >> 3;
    int li = lane & 7;

    // per-thread load slots (4 x 16B for A, 4 x 16B for B per chunk)
    int lr = tid >> 1;                 // row pair base: idx = tid + i*256 -> r = idx>>3
    (void)lr;

    float acc[2][8][4];
#pragma unroll
    for (int i = 0; i < 2; i++)
#pragma unroll
        for (int j = 0; j < 8; j++)
#pragma unroll
            for (int k = 0; k < 4; k++) acc[i][j][k] = 0.f;

    auto prefetch = [&](int ch, int st) {
        int k2 = ch * 32;
#pragma unroll
        for (int i = 0; i < 4; i++) {
            int idx = tid + i * 256;
            int r = idx >> 3;
            int c2 = (idx & 7) * 4;
            int gr = rowBase + r;
            uint32_t adst = (uint32_t)__cvta_generic_to_shared(Abuf[st] + r * TPAD + c2);
            cp_async16(adst, g_sh + (size_t)gr * 128 + k2 + c2, gr < NN ? 16 : 0);
            uint32_t bdst = (uint32_t)__cvta_generic_to_shared(Bbuf[st] + r * TPAD + c2);
            cp_async16(bdst, wTl + (size_t)(colBase + r) * 128 + k2 + c2, 16);
        }
        CP_COMMIT();
    };

    prefetch(0, 0);
    for (int ch = 0; ch < 4; ch++) {
        int st = ch & 1;
        CP_WAIT0();
        __syncthreads();
        if (ch < 3) prefetch(ch + 1, st ^ 1);
        __half2* As = Abuf[st];
        __half2* Bs = Bbuf[st];
#pragma unroll
        for (int kk2 = 0; kk2 < 32; kk2 += 8) {
            uint32_t a[2][4];
#pragma unroll
            for (int ma = 0; ma < 2; ma++) {
                uint32_t addr = (uint32_t)__cvta_generic_to_shared(
                    As + (mRow + ma * 16 + (lt & 1) * 8 + li) * TPAD + kk2 + (lt >> 1) * 4);
                LDSM_X4(a[ma][0], a[ma][1], a[ma][2], a[ma][3], addr);
            }
            uint32_t b[8][2];
#pragma unroll
            for (int nb = 0; nb < 8; nb += 2) {
                uint32_t addr = (uint32_t)__cvta_generic_to_shared(
                    Bs + (nBase + nb * 8 + (lt >> 1) * 8 + li) * TPAD + kk2 + (lt & 1) * 4);
                uint32_t r0, r1, r2, r3;
                LDSM_X4(r0, r1, r2, r3, addr);
                b[nb][0] = r0; b[nb][1] = r1;
                b[nb + 1][0] = r2; b[nb + 1][1] = r3;
            }
#pragma unroll
            for (int nb = 0; nb < 8; nb++)
#pragma unroll
                for (int ma = 0; ma < 2; ma++)
                    MMA_F16(acc[ma][nb], a[ma][0], a[ma][1], a[ma][2], a[ma][3],
                            b[nb][0], b[nb][1]);
        }
        __syncthreads();
    }

#pragma unroll
    for (int ma = 0; ma < 2; ma++) {
        int r0 = rowBase + mRow + ma * 16 + quadRow;
        int r1 = r0 + 8;
#pragma unroll
        for (int nb = 0; nb < 8; nb++) {
            int c = colBase + nBase + nb * 8 + quadCol * 2;
            if (r0 < NN)
                g_hh[(size_t)r0 * 128 + (c >> 1)] = __floats2half2_rn(
                    fmaxf(acc[ma][nb][0], 0.f), fmaxf(acc[ma][nb][1], 0.f));
            if (r1 < NN)
                g_hh[(size_t)r1 * 128 + (c >> 1)] = __floats2half2_rn(
                    fmaxf(acc[ma][nb][2], 0.f), fmaxf(acc[ma][nb][3], 0.f));
        }
    }
}

// projection GEMM fp16: h0 = x @ projW + b (pipelined, 16 K-chunks)
__global__ __launch_bounds__(256, 2) void k_gemm_proj(const float* __restrict__ bias) {
    extern __shared__ __half2 dsm[];
    __half2* Abuf[2] = { dsm, dsm + STAGE_H2 };
    __half2* Bbuf[2] = { dsm + 2 * STAGE_H2, dsm + 3 * STAGE_H2 };

    int tid = threadIdx.x;
    int wid = tid >> 5;
    int lane = tid & 31;
    int quadRow = lane >> 2;
    int quadCol = lane & 3;
    int warpM = wid >> 1;
    int warpN = wid & 1;
    int mRow = warpM * 32;
    int nBase = warpN * 64;
    int rowBase = blockIdx.x * 128;
    int colBase = blockIdx.y * 128;

    int lt = lane >> 3;
    int li = lane & 7;

    float acc[2][8][4];
#pragma unroll
    for (int i = 0; i < 2; i++)
#pragma unroll
        for (int j = 0; j < 8; j++)
#pragma unroll
            for (int k = 0; k < 4; k++) acc[i][j][k] = 0.f;

    auto prefetch = [&](int ch, int st) {
        int k2 = ch * 32;
#pragma unroll
        for (int i = 0; i < 4; i++) {
            int idx = tid + i * 256;
            int r = idx >> 3;
            int c2 = (idx & 7) * 4;
            int gr = rowBase + r;
            uint32_t adst = (uint32_t)__cvta_generic_to_shared(Abuf[st] + r * TPAD + c2);
            cp_async16(adst, g_xh + (size_t)gr * 512 + k2 + c2, gr < NN ? 16 : 0);
            uint32_t bdst = (uint32_t)__cvta_generic_to_shared(Bbuf[st] + r * TPAD + c2);
            cp_async16(bdst, g_pWh + (size_t)(colBase + r) * 512 + k2 + c2, 16);
        }
        CP_COMMIT();
    };

    prefetch(0, 0);
    for (int ch = 0; ch < 16; ch++) {
        int st = ch & 1;
        CP_WAIT0();
        __syncthreads();
        if (ch < 15) prefetch(ch + 1, st ^ 1);
        __half2* As = Abuf[st];
        __half2* Bs = Bbuf[st];
#pragma unroll
        for (int kk2 = 0; kk2 < 32; kk2 += 8) {
            uint32_t a[2][4];
#pragma unroll
            for (int ma = 0; ma < 2; ma++) {
                uint32_t addr = (uint32_t)__cvta_generic_to_shared(
                    As + (mRow + ma * 16 + (lt & 1) * 8 + li) * TPAD + kk2 + (lt >> 1) * 4);
                LDSM_X4(a[ma][0], a[ma][1], a[ma][2], a[ma][3], addr);
            }
            uint32_t b[8][2];
#pragma unroll
            for (int nb = 0; nb < 8; nb += 2) {
                uint32_t addr = (uint32_t)__cvta_generic_to_shared(
                    Bs + (nBase + nb * 8 + (lt >> 1) * 8 + li) * TPAD + kk2 + (lt & 1) * 4);
                uint32_t r0, r1, r2, r3;
                LDSM_X4(r0, r1, r2, r3, addr);
                b[nb][0] = r0; b[nb][1] = r1;
                b[nb + 1][0] = r2; b[nb + 1][1] = r3;
            }
#pragma unroll
            for (int nb = 0; nb < 8; nb++)
#pragma unroll
                for (int ma = 0; ma < 2; ma++)
                    MMA_F16(acc[ma][nb], a[ma][0], a[ma][1], a[ma][2], a[ma][3],
                            b[nb][0], b[nb][1]);
        }
        __syncthreads();
    }

#pragma unroll
    for (int ma = 0; ma < 2; ma++) {
        int r0 = rowBase + mRow + ma * 16 + quadRow;
        int r1 = r0 + 8;
#pragma unroll
        for (int nb = 0; nb < 8; nb++) {
            int c = colBase + nBase + nb * 8 + quadCol * 2;
            float bx = bias[c], by = bias[c + 1];
            if (r0 < NN)
                g_h0h[(size_t)r0 * 128 + (c >> 1)] =
                    __floats2half2_rn(acc[ma][nb][0] + bx, acc[ma][nb][1] + by);
            if (r1 < NN)
                g_h0h[(size_t)r1 * 128 + (c >> 1)] =
                    __floats2half2_rn(acc[ma][nb][2] + bx, acc[ma][nb][3] + by);
        }
    }
}

// ---------------- classifier (reads fp16 h) ----------------
__global__ void k_cls(const float* __restrict__ Wc, const float* __restrict__ bc,
                      float* __restrict__ out) {
    int gw   = (blockIdx.x * blockDim.x + threadIdx.x) >> 5;
    int lane = threadIdx.x & 31;
    if (gw >= NN) return;
    const __half2* hr = g_hh + (size_t)gw * 128;
    float a0 = 0.f, a1 = 0.f, a2 = 0.f, a3 = 0.f;
    for (int k2 = lane; k2 < 128; k2 += 32) {
        float2 hv = __half22float2(hr[k2]);
        const float* w0 = Wc + (k2 * 2) * CC;
        a0 = fmaf(hv.x, w0[0], a0); a1 = fmaf(hv.x, w0[1], a1);
        a2 = fmaf(hv.x, w0[2], a2); a3 = fmaf(hv.x, w0[3], a3);
        a0 = fmaf(hv.y, w0[4], a0); a1 = fmaf(hv.y, w0[5], a1);
        a2 = fmaf(hv.y, w0[6], a2); a3 = fmaf(hv.y, w0[7], a3);
    }
#pragma unroll
    for (int off = 16; off; off >>= 1) {
        a0 += __shfl_down_sync(0xffffffffu, a0, off);
        a1 += __shfl_down_sync(0xffffffffu, a1, off);
        a2 += __shfl_down_sync(0xffffffffu, a2, off);
        a3 += __shfl_down_sync(0xffffffffu, a3, off);
    }
    if (lane == 0) {
        out[gw * CC + 0] = a0 + bc[0];
        out[gw * CC + 1] = a1 + bc[1];
        out[gw * CC + 2] = a2 + bc[2];
        out[gw * CC + 3] = a3 + bc[3];
    }
}

// ---------------- launch ----------------

extern "C" void kernel_launch(void* const* d_in, const int* in_sizes, int n_in,
                              void* d_out, int out_size) {
    const float* x     = (const float*)d_in[0];
    const int*   ei    = (const int*)  d_in[1];
    const float* projW = (const float*)d_in[2];
    const float* projb = (const float*)d_in[3];
    const float* wts   = (const float*)d_in[4];
    const float* clsW  = (const float*)d_in[5];
    const float* clsb  = (const float*)d_in[6];
    float* out = (float*)d_out;

    const int* src = ei;
    const int* dst = ei + EE;

    static int attrDone = 0;
    if (!attrDone) {
        cudaFuncSetAttribute(k_gemm_mma, cudaFuncAttributeMaxDynamicSharedMemorySize, GEMM_SMEM);
        cudaFuncSetAttribute(k_gemm_proj, cudaFuncAttributeMaxDynamicSharedMemorySize, GEMM_SMEM);
        attrDone = 1;
    }

    k_init_deg<<<(NN + 255) / 256, 256>>>();
    k_count   <<<(EE + 255) / 256, 256>>>(dst);
    k_dinv    <<<(NN + 255) / 256, 256>>>();
    k_scan    <<<1, 1024>>>();
    k_selfloop<<<(NN + 255) / 256, 256>>>();
    k_fill    <<<(EE + 255) / 256, 256>>>(src, dst);

    dim3 tg(HH / 32, HH / 32, LL);
    k_transpose_w<<<tg, dim3(32, 8)>>>(wts);
    dim3 pg(HH / 32, DIN / 32);
    k_transpose_pw<<<pg, dim3(32, 8)>>>(projW);
    k_x2h<<<(NN * DIN / 4 + 255) / 256, 256>>>(x);

    dim3 gg((NN + 127) / 128, 2);
    k_gemm_proj<<<gg, 256, GEMM_SMEM>>>(projb);

    dim3 mg((NN + 127) / 128, HH / 128);
    for (int l = 0; l < LL; l++) {
        k_spmm<<<NN, 128>>>(l == 0 ? 1 : 0);
        k_gemm_mma<<<mg, 256, GEMM_SMEM>>>(l);
    }

    k_cls<<<(NN * 32 + 255) / 256, 256>>>(clsW, clsb, out);
}